// round 14
// baseline (speedup 1.0000x reference)
#include <cuda_runtime.h>
#include <cuda_fp16.h>
#include <math.h>

#define B_  8
#define S_  256
#define H_  768
#define L_  12
#define NH_ 12
#define D_  64
#define FF_ 3072
#define NL_ 9
#define M_  (B_*S_)   // 2048 token rows

// ---------------- scratch (device globals: allowed, no allocations) ---------
__device__ float  g_h  [M_*H_];    // fp32 residual stream
__device__ __half g_hh [M_*H_];    // fp16 copy (GEMM A operand)
__device__ __half g_qh [M_*H_];    // fp16 q/k/v (attention inputs)
__device__ __half g_kh [M_*H_];
__device__ __half g_vh [M_*H_];
__device__ __half g_ctxh[M_*H_];   // fp16 attn context (O-proj A operand)
__device__ float  g_tmp[M_*H_];
__device__ __half g_ffh[M_*FF_];   // fp16 FFN1 output (FFN2 A operand)
__device__ float  g_cmp[M_*H_];
__device__ float  g_bias[M_];
__device__ int    g_order[M_];

// fp16 weights, TRANSPOSED to [N][K] per layer (converted once per launch)
__device__ __half g_tWq [L_*H_*H_];
__device__ __half g_tWk [L_*H_*H_];
__device__ __half g_tWv [L_*H_*H_];
__device__ __half g_tWo [L_*H_*H_];
__device__ __half g_tWi [L_*H_*FF_];
__device__ __half g_tWo2[L_*FF_*H_];

// ---------------- helpers ------------------------------------------------
#define MMA_F16(acc, a, b)                                                   \
    asm volatile(                                                            \
        "mma.sync.aligned.m16n8k16.row.col.f32.f16.f16.f32 "                 \
        "{%0,%1,%2,%3},{%4,%5,%6,%7},{%8,%9},{%0,%1,%2,%3};\n"               \
        : "+f"(acc[0]), "+f"(acc[1]), "+f"(acc[2]), "+f"(acc[3])             \
        : "r"(a[0]), "r"(a[1]), "r"(a[2]), "r"(a[3]), "r"(b[0]), "r"(b[1]))

#define LDSM4(r, addr)                                                       \
    asm volatile(                                                            \
        "ldmatrix.sync.aligned.m8n8.x4.shared.b16 {%0,%1,%2,%3}, [%4];"      \
        : "=r"((r)[0]), "=r"((r)[1]), "=r"((r)[2]), "=r"((r)[3])             \
        : "r"(addr))

__device__ __forceinline__ void cp16(void* smem, const void* g) {
    unsigned s = (unsigned)__cvta_generic_to_shared(smem);
    asm volatile("cp.async.cg.shared.global [%0], [%1], 16;\n" :: "r"(s), "l"(g));
}
__device__ __forceinline__ void cp_commit() {
    asm volatile("cp.async.commit_group;\n");
}
template<int N> __device__ __forceinline__ void cp_wait() {
    asm volatile("cp.async.wait_group %0;\n" :: "n"(N));
}

// ---------------- weight fp16 convert + transpose ----------------------------
__global__ __launch_bounds__(256) void cvtT_kernel(
    const float* __restrict__ in, __half* __restrict__ out, int K, int N)
{
    __shared__ __half sm[32][33];
    const float* inL  = in  + (size_t)blockIdx.z * K * N;
    __half*      outL = out + (size_t)blockIdx.z * K * N;
    const int n0 = blockIdx.x * 32, k0 = blockIdx.y * 32;
    const int tid = threadIdx.x;

    #pragma unroll
    for (int i = 0; i < 4; i++) {
        int idx = tid + i*256;
        int k = idx >> 5, n = idx & 31;
        sm[n][k] = __float2half(inL[(size_t)(k0 + k) * N + n0 + n]);
    }
    __syncthreads();

    if (tid < 128) {
        int n  = tid >> 2;
        int k8 = (tid & 3) << 3;
        __half v[8];
        #pragma unroll
        for (int j = 0; j < 8; j++) v[j] = sm[n][k8 + j];
        *(uint4*)&outL[(size_t)(n0 + n) * K + k0 + k8] = *(uint4*)v;
    }
}

// ---------------- fused (sum, sumsq) block reduce (256 thr) ------------------
__device__ __forceinline__ void block_sum2(float a, float b, float* ws, int t,
                                           float& outa, float& outb) {
    #pragma unroll
    for (int o = 16; o > 0; o >>= 1) {
        a += __shfl_xor_sync(0xffffffffu, a, o);
        b += __shfl_xor_sync(0xffffffffu, b, o);
    }
    if ((t & 31) == 0) { ws[t >> 5] = a; ws[8 + (t >> 5)] = b; }
    __syncthreads();
    float ta = 0.f, tb = 0.f;
    #pragma unroll
    for (int w = 0; w < 8; w++) { ta += ws[w]; tb += ws[8 + w]; }
    outa = ta; outb = tb;
}

// ---------------- embeddings + LayerNorm (dual write fp32+fp16) -------------
__global__ __launch_bounds__(256) void embed_kernel(
    const int* __restrict__ ids, const int* __restrict__ types,
    const float* __restrict__ we, const float* __restrict__ pe,
    const float* __restrict__ te,
    const float* __restrict__ g, const float* __restrict__ bta)
{
    int row = blockIdx.x;
    int s   = row % S_;
    int t   = threadIdx.x;
    __shared__ float ws[16];

    int id = ids[row];
    int ty = types[row];
    float x0 = we[id*H_ + t]       + pe[s*H_ + t]       + te[ty*H_ + t];
    float x1 = we[id*H_ + t + 256] + pe[s*H_ + t + 256] + te[ty*H_ + t + 256];
    float x2 = we[id*H_ + t + 512] + pe[s*H_ + t + 512] + te[ty*H_ + t + 512];

    float ts, ts2;
    block_sum2(x0 + x1 + x2, x0*x0 + x1*x1 + x2*x2, ws, t, ts, ts2);
    float mean = ts * (1.0f / H_);
    float var  = ts2 * (1.0f / H_) - mean * mean;
    float rstd = rsqrtf(var + 1e-12f);

    float o0 = (x0 - mean)*rstd*g[t]     + bta[t];
    float o1 = (x1 - mean)*rstd*g[t+256] + bta[t+256];
    float o2 = (x2 - mean)*rstd*g[t+512] + bta[t+512];
    g_h [row*H_ + t]       = o0;  g_hh[row*H_ + t]       = __float2half(o0);
    g_h [row*H_ + t + 256] = o1;  g_hh[row*H_ + t + 256] = __float2half(o1);
    g_h [row*H_ + t + 512] = o2;  g_hh[row*H_ + t + 512] = __float2half(o2);
}

// ---------------- generic LayerNorm (dual write) ------------------------------
__global__ __launch_bounds__(256) void ln_kernel(
    const float* __restrict__ in, const float* __restrict__ g,
    const float* __restrict__ bta, float* __restrict__ outf,
    __half* __restrict__ outh)
{
    int row = blockIdx.x, t = threadIdx.x;
    __shared__ float ws[16];
    const float* xr = in + row*H_;
    float x0 = xr[t], x1 = xr[t + 256], x2 = xr[t + 512];

    float ts, ts2;
    block_sum2(x0 + x1 + x2, x0*x0 + x1*x1 + x2*x2, ws, t, ts, ts2);
    float mean = ts * (1.0f / H_);
    float var  = ts2 * (1.0f / H_) - mean * mean;
    float rstd = rsqrtf(var + 1e-12f);

    float o0 = (x0 - mean)*rstd*g[t]     + bta[t];
    float o1 = (x1 - mean)*rstd*g[t+256] + bta[t+256];
    float o2 = (x2 - mean)*rstd*g[t+512] + bta[t+512];
    outf[row*H_ + t]       = o0;  outh[row*H_ + t]       = __float2half(o0);
    outf[row*H_ + t + 256] = o1;  outh[row*H_ + t + 256] = __float2half(o1);
    outf[row*H_ + t + 512] = o2;  outh[row*H_ + t + 512] = __float2half(o2);
}

// ---------------- attention mask bias ----------------------------------------
__global__ void bias_kernel(const int* __restrict__ mask)
{
    int i = blockIdx.x * 256 + threadIdx.x;
    if (i < M_) g_bias[i] = (1.0f - (float)mask[i]) * -1e4f;
}

// ---------------- fp16 cp.async GEMM, ldmatrix fragment loads ----------------
#define HST 72   // smem row stride in halves (144 B; 16B-aligned rows)

template<int BM, int MT>
__global__ __launch_bounds__(256, 2) void gemm_h(
    const __half* __restrict__ A,
    const __half* __restrict__ W0, const __half* __restrict__ W1, const __half* __restrict__ W2,
    const float* __restrict__ bi0, const float* __restrict__ bi1, const float* __restrict__ bi2,
    float* __restrict__ Cf0, float* __restrict__ Cf1, float* __restrict__ Cf2,
    __half* __restrict__ Ch0, __half* __restrict__ Ch1, __half* __restrict__ Ch2,
    const float* __restrict__ res, int M, int N, int K, int act)
{
    const __half* Bt   = (blockIdx.z == 0) ? W0 : (blockIdx.z == 1 ? W1 : W2);
    const float*  bias = (blockIdx.z == 0) ? bi0 : (blockIdx.z == 1 ? bi1 : bi2);
    float*        Cf   = (blockIdx.z == 0) ? Cf0 : (blockIdx.z == 1 ? Cf1 : Cf2);
    __half*       Ch   = (blockIdx.z == 0) ? Ch0 : (blockIdx.z == 1 ? Ch1 : Ch2);

    constexpr int ASZ = BM  * HST;
    constexpr int BSZ = 128 * HST;
    extern __shared__ __half smh[];

    const int tid  = threadIdx.x;
    const int row0 = blockIdx.y * BM;
    const int col0 = blockIdx.x * 128;

    const int warp = tid >> 5, lane = tid & 31;
    const int wm = warp >> 2, wn = warp & 3;
    const int grp = lane >> 2, tg = lane & 3;

    const int lrowA = lane & 15;
    const int lcolA = (lane >> 4) * 8;
    const int lrowB = (lane & 7) + ((lane >> 4) & 1) * 8;
    const int lcolB = ((lane >> 3) & 1) * 8;

    const unsigned smemBase = (unsigned)__cvta_generic_to_shared(smh);
    unsigned offA[MT], offB[2];
    #pragma unroll
    for (int mt = 0; mt < MT; mt++)
        offA[mt] = (unsigned)(((wm*(BM/2) + mt*16 + lrowA)*HST + lcolA) * 2);
    #pragma unroll
    for (int p = 0; p < 2; p++)
        offB[p] = (unsigned)(((wn*32 + p*16 + lrowB)*HST + lcolB) * 2 + ASZ*2);

    float acc[MT][4][4];
    #pragma unroll
    for (int mt = 0; mt < MT; mt++)
        #pragma unroll
        for (int nt = 0; nt < 4; nt++)
            #pragma unroll
            for (int c = 0; c < 4; c++) acc[mt][nt][c] = 0.f;

    const __half* Ag = A  + (size_t)row0 * K;
    const __half* Bg = Bt + (size_t)col0 * K;

    auto issue = [&](int it, int buf) {
        __half* As = smh + buf * (ASZ + BSZ);
        __half* Bs = As + ASZ;
        const int kk = it * 64;
        #pragma unroll
        for (int p = 0; p < BM*8/256; p++) {
            int idx = tid + p*256;
            int r = idx >> 3, c8 = (idx & 7) << 3;
            cp16(&As[r*HST + c8], Ag + (size_t)r*K + kk + c8);
        }
        #pragma unroll
        for (int p = 0; p < 4; p++) {
            int idx = tid + p*256;
            int n = idx >> 3, c8 = (idx & 7) << 3;
            cp16(&Bs[n*HST + c8], Bg + (size_t)n*K + kk + c8);
        }
        cp_commit();
    };

    const int nIter = K >> 6;
    issue(0, 0);

    for (int it = 0; it < nIter; it++) {
        const int buf = it & 1;
        if (it + 1 < nIter) { issue(it + 1, buf ^ 1); cp_wait<1>(); }
        else                { cp_wait<0>(); }
        __syncthreads();

        const unsigned bufBase = smemBase + (unsigned)(buf * (ASZ + BSZ) * 2);

        #pragma unroll
        for (int ks = 0; ks < 4; ks++) {
            const unsigned kb = (unsigned)(ks * 32);
            unsigned af[MT][4], bf0[4], bf1[4];
            #pragma unroll
            for (int mt = 0; mt < MT; mt++)
                LDSM4(af[mt], bufBase + offA[mt] + kb);
            LDSM4(bf0, bufBase + offB[0] + kb);
            LDSM4(bf1, bufBase + offB[1] + kb);
            #pragma unroll
            for (int mt = 0; mt < MT; mt++) {
                MMA_F16(acc[mt][0], af[mt], (bf0 + 0));
                MMA_F16(acc[mt][1], af[mt], (bf0 + 2));
                MMA_F16(acc[mt][2], af[mt], (bf1 + 0));
                MMA_F16(acc[mt][3], af[mt], (bf1 + 2));
            }
        }
        __syncthreads();
    }

    #pragma unroll
    for (int mt = 0; mt < MT; mt++) {
        #pragma unroll
        for (int nt = 0; nt < 4; nt++) {
            int r0 = row0 + wm*(BM/2) + mt*16 + grp;
            int r1 = r0 + 8;
            int c  = col0 + wn*32 + nt*8 + 2*tg;
            float b0 = bias[c], b1 = bias[c+1];
            float v00 = acc[mt][nt][0] + b0, v01 = acc[mt][nt][1] + b1;
            float v10 = acc[mt][nt][2] + b0, v11 = acc[mt][nt][3] + b1;
            if (res) {
                v00 += res[(size_t)r0*N + c];     v01 += res[(size_t)r0*N + c + 1];
                v10 += res[(size_t)r1*N + c];     v11 += res[(size_t)r1*N + c + 1];
            }
            if (act) {
                v00 = 0.5f*v00*(1.0f + erff(v00*0.70710678118654752f));
                v01 = 0.5f*v01*(1.0f + erff(v01*0.70710678118654752f));
                v10 = 0.5f*v10*(1.0f + erff(v10*0.70710678118654752f));
                v11 = 0.5f*v11*(1.0f + erff(v11*0.70710678118654752f));
            }
            if (Cf) {
                *(float2*)&Cf[(size_t)r0*N + c] = make_float2(v00, v01);
                *(float2*)&Cf[(size_t)r1*N + c] = make_float2(v10, v11);
            }
            if (Ch) {
                *(__half2*)&Ch[(size_t)r0*N + c] = __floats2half2_rn(v00, v01);
                *(__half2*)&Ch[(size_t)r1*N + c] = __floats2half2_rn(v10, v11);
            }
        }
    }
}

// ---------------- fp16 fused attention (phase-1 LDSM, phase-2 scalar) --------
#define AT_KOFF 0
#define AT_QOFF (256*72)
#define AT_VOFF (256*72 + 64*72)
#define AT_FOFF (AT_VOFF + 64*264)
#define AT_SMEM (AT_FOFF*2 + (256 + 256 + 256)*4)

__global__ __launch_bounds__(256, 2) void attn_h()
{
    const int qt = blockIdx.x, h = blockIdx.y, b = blockIdx.z;
    const int q0 = qt * 64;
    const int tid = threadIdx.x;
    const int warp = tid >> 5, lane = tid & 31;
    const int grp = lane >> 2, tg = lane & 3;
    const int wm = warp >> 2, wn = warp & 3;

    extern __shared__ __half smh[];
    __half* Ks = smh + AT_KOFF;
    __half* Qs = smh + AT_QOFF;
    __half* Vt = smh + AT_VOFF;
    __half* Ps = smh;
    float* fb     = (float*)(smh + AT_FOFF);
    float* bias_s = fb;
    float* pmax   = fb + 256;
    float* psum   = fb + 512;

    const __half* Kg = g_kh + (size_t)(b*S_)*H_ + h*D_;
    #pragma unroll
    for (int i = 0; i < 8; i++) {
        int idx = i*256 + tid;
        int r = idx >> 3, c = (idx & 7) << 3;
        cp16(&Ks[r*72 + c], Kg + (size_t)r*H_ + c);
    }
    const __half* Qg = g_qh + (size_t)(b*S_ + q0)*H_ + h*D_;
    #pragma unroll
    for (int i = 0; i < 2; i++) {
        int idx = i*256 + tid;
        int r = idx >> 3, c = (idx & 7) << 3;
        cp16(&Qs[r*72 + c], Qg + (size_t)r*H_ + c);
    }
    cp_commit();

    const __half* Vg = g_vh + (size_t)(b*S_)*H_ + h*D_;
    #pragma unroll
    for (int i = 0; i < 8; i++) {
        int idx = i*256 + tid;
        int k = idx >> 3, d = (idx & 7) << 3;
        uint4 v = *(const uint4*)(Vg + (size_t)k*H_ + d);
        __half hv[8];
        *(uint4*)hv = v;
        #pragma unroll
        for (int j = 0; j < 8; j++) Vt[(d+j)*264 + k] = hv[j];
    }
    bias_s[tid] = g_bias[b*S_ + tid];
    cp_wait<0>();
    __syncthreads();

    // ---- phase 1: scores = Q @ K^T (ldmatrix fragments, verified stride-72) --
    float acc1[2][8][4];
    #pragma unroll
    for (int mt = 0; mt < 2; mt++)
        #pragma unroll
        for (int nt = 0; nt < 8; nt++)
            #pragma unroll
            for (int c = 0; c < 4; c++) acc1[mt][nt][c] = 0.f;

    {
        const int lrowA = lane & 15;
        const int lcolA = (lane >> 4) * 8;
        const int lrowB = (lane & 7) + ((lane >> 4) & 1) * 8;
        const int lcolB = ((lane >> 3) & 1) * 8;
        const unsigned smemBase = (unsigned)__cvta_generic_to_shared(smh);

        unsigned offQ[2], offK[4];
        #pragma unroll
        for (int mt = 0; mt < 2; mt++)
            offQ[mt] = (unsigned)(AT_QOFF*2 + ((wm*32 + mt*16 + lrowA)*72 + lcolA)*2);
        #pragma unroll
        for (int p = 0; p < 4; p++)
            offK[p] = (unsigned)(((wn*64 + p*16 + lrowB)*72 + lcolB)*2);

        #pragma unroll
        for (int ks = 0; ks < 4; ks++) {
            const unsigned kb = (unsigned)(ks * 32);
            unsigned af[2][4], bf[4][4];
            #pragma unroll
            for (int mt = 0; mt < 2; mt++)
                LDSM4(af[mt], smemBase + offQ[mt] + kb);
            #pragma unroll
            for (int p = 0; p < 4; p++)
                LDSM4(bf[p], smemBase + offK[p] + kb);
            #pragma unroll
            for (int mt = 0; mt < 2; mt++)
                #pragma unroll
                for (int p = 0; p < 4; p++) {
                    MMA_F16(acc1[mt][p*2],   af[mt], (bf[p] + 0));
                    MMA_F16(acc1[mt][p*2+1], af[mt], (bf[p] + 2));
                }
        }
    }

    // ---- scale + bias in regs; row max via shfl + smem ----
    float rmax[2][2];
    #pragma unroll
    for (int mt = 0; mt < 2; mt++) { rmax[mt][0] = -1e30f; rmax[mt][1] = -1e30f; }
    #pragma unroll
    for (int mt = 0; mt < 2; mt++)
        #pragma unroll
        for (int p = 0; p < 4; p++)
            #pragma unroll
            for (int q = 0; q < 2; q++) {
                int nt = p*2 + q;
                int c = wn*64 + p*16 + q*8 + 2*tg;
                float b0 = bias_s[c], b1 = bias_s[c+1];
                acc1[mt][nt][0] = acc1[mt][nt][0]*0.125f + b0;
                acc1[mt][nt][1] = acc1[mt][nt][1]*0.125f + b1;
                acc1[mt][nt][2] = acc1[mt][nt][2]*0.125f + b0;
                acc1[mt][nt][3] = acc1[mt][nt][3]*0.125f + b1;
                rmax[mt][0] = fmaxf(rmax[mt][0], fmaxf(acc1[mt][nt][0], acc1[mt][nt][1]));
                rmax[mt][1] = fmaxf(rmax[mt][1], fmaxf(acc1[mt][nt][2], acc1[mt][nt][3]));
            }
    #pragma unroll
    for (int mt = 0; mt < 2; mt++)
        #pragma unroll
        for (int hh = 0; hh < 2; hh++) {
            float m = rmax[mt][hh];
            m = fmaxf(m, __shfl_xor_sync(0xffffffffu, m, 1));
            m = fmaxf(m, __shfl_xor_sync(0xffffffffu, m, 2));
            rmax[mt][hh] = m;
        }
    if (tg == 0) {
        #pragma unroll
        for (int mt = 0; mt < 2; mt++) {
            pmax[(wm*32 + mt*16 + grp)*4 + wn]     = rmax[mt][0];
            pmax[(wm*32 + mt*16 + grp + 8)*4 + wn] = rmax[mt][1];
        }
    }
    __syncthreads();   // gates: all K reads done -> Ps alias writable

    // ---- exp (regs), write fp16 P, partial sums ----
    float rsum[2][2] = {{0.f,0.f},{0.f,0.f}};
    #pragma unroll
    for (int mt = 0; mt < 2; mt++) {
        int lr0 = wm*32 + mt*16 + grp, lr1 = lr0 + 8;
        float m0 = fmaxf(fmaxf(pmax[lr0*4+0], pmax[lr0*4+1]), fmaxf(pmax[lr0*4+2], pmax[lr0*4+3]));
        float m1 = fmaxf(fmaxf(pmax[lr1*4+0], pmax[lr1*4+1]), fmaxf(pmax[lr1*4+2], pmax[lr1*4+3]));
        #pragma unroll
        for (int p = 0; p < 4; p++)
            #pragma unroll
            for (int q = 0; q < 2; q++) {
                int nt = p*2 + q;
                int c = wn*64 + p*16 + q*8 + 2*tg;
                float e0 = __expf(acc1[mt][nt][0] - m0);
                float e1 = __expf(acc1[mt][nt][1] - m0);
                float e2 = __expf(acc1[mt][nt][2] - m1);
                float e3 = __expf(acc1[mt][nt][3] - m1);
                rsum[mt][0] += e0 + e1;
                rsum[mt][1] += e2 + e3;
                *(__half2*)&Ps[lr0*264 + c] = __floats2half2_rn(e0, e1);
                *(__half2*)&Ps[lr1*264 + c] = __floats2half2_rn(e2, e3);
            }
    }
    #pragma unroll
    for (int mt = 0; mt < 2; mt++)
        #pragma unroll
        for (int hh = 0; hh < 2; hh++) {
            float s = rsum[mt][hh];
            s += __shfl_xor_sync(0xffffffffu, s, 1);
            s += __shfl_xor_sync(0xffffffffu, s, 2);
            rsum[mt][hh] = s;
        }
    if (tg == 0) {
        #pragma unroll
        for (int mt = 0; mt < 2; mt++) {
            psum[(wm*32 + mt*16 + grp)*4 + wn]     = rsum[mt][0];
            psum[(wm*32 + mt*16 + grp + 8)*4 + wn] = rsum[mt][1];
        }
    }
    __syncthreads();

    // ---- phase 2: ctx = P @ V (scalar fragment loads; stride-264 quarantined)
    float acc2[2][2][4];
    #pragma unroll
    for (int mt = 0; mt < 2; mt++)
        #pragma unroll
        for (int nt = 0; nt < 2; nt++)
            #pragma unroll
            for (int c = 0; c < 4; c++) acc2[mt][nt][c] = 0.f;

    {
        const unsigned* Pw = (const unsigned*)Ps;
        const unsigned* Vw = (const unsigned*)Vt;
        #pragma unroll 4
        for (int ks = 0; ks < 16; ks++) {
            const int kw = ks * 8;
            unsigned af[2][4], bf[2][2];
            #pragma unroll
            for (int mt = 0; mt < 2; mt++) {
                const unsigned* Ar = Pw + (wm*32 + mt*16 + grp)*132;
                af[mt][0] = Ar[kw + tg];
                af[mt][1] = Ar[8*132 + kw + tg];
                af[mt][2] = Ar[kw + tg + 4];
                af[mt][3] = Ar[8*132 + kw + tg + 4];
            }
            #pragma unroll
            for (int nt = 0; nt < 2; nt++) {
                const unsigned* Br = Vw + (wn*16 + nt*8 + grp)*132;
                bf[nt][0] = Br[kw + tg];
                bf[nt][1] = Br[kw + tg + 4];
            }
            #pragma unroll
            for (int mt = 0; mt < 2; mt++)
                #pragma unroll
                for (int nt = 0; nt < 2; nt++)
                    MMA_F16(acc2[mt][nt], af[mt], bf[nt]);
        }
    }

    #pragma unroll
    for (int mt = 0; mt < 2; mt++) {
        int lr0 = wm*32 + mt*16 + grp, lr1 = lr0 + 8;
        float i0 = 1.0f / (psum[lr0*4+0] + psum[lr0*4+1] + psum[lr0*4+2] + psum[lr0*4+3]);
        float i1 = 1.0f / (psum[lr1*4+0] + psum[lr1*4+1] + psum[lr1*4+2] + psum[lr1*4+3]);
        #pragma unroll
        for (int nt = 0; nt < 2; nt++) {
            int c = wn*16 + nt*8 + 2*tg;
            __half* o0 = g_ctxh + (size_t)(b*S_ + q0 + lr0)*H_ + h*D_ + c;
            __half* o1 = g_ctxh + (size_t)(b*S_ + q0 + lr1)*H_ + h*D_ + c;
            *(__half2*)o0 = __floats2half2_rn(acc2[mt][nt][0]*i0, acc2[mt][nt][1]*i0);
            *(__half2*)o1 = __floats2half2_rn(acc2[mt][nt][2]*i1, acc2[mt][nt][3]*i1);
        }
    }
}

// ---------------- stable compaction order per batch --------------------------
__global__ __launch_bounds__(256) void order_kernel(const int* __restrict__ valid)
{
    int b = blockIdx.x, t = threadIdx.x;
    __shared__ int sc[256];
    __shared__ int ord[256];
    int v = valid[b*S_ + t];
    sc[t] = v; __syncthreads();
    for (int off = 1; off < 256; off <<= 1) {
        int x = (t >= off) ? sc[t - off] : 0;
        __syncthreads();
        sc[t] += x;
        __syncthreads();
    }
    ord[t] = -1; __syncthreads();
    if (v) ord[sc[t] - v] = t;
    __syncthreads();
    g_order[b*S_ + t] = ord[t];
}

__global__ __launch_bounds__(256) void compact_kernel()
{
    int row = blockIdx.x;
    int b = row / S_;
    int src = g_order[row];
    int t = threadIdx.x;
    if (src < 0) {
        for (int e = t; e < H_; e += 256) g_cmp[row*H_ + e] = 0.f;
    } else {
        const float* xp = g_h + (b*S_ + src)*H_;
        for (int e = t; e < H_; e += 256) g_cmp[row*H_ + e] = xp[e];
    }
}

// ---------------- classifier + softmax ---------------------------------------
__global__ __launch_bounds__(256) void clf_kernel(
    const float* __restrict__ W, const float* __restrict__ bias,
    float* __restrict__ outp)
{
    int row = blockIdx.x, t = threadIdx.x;
    __shared__ float red[256][NL_ + 1];
    float p[NL_];
    #pragma unroll
    for (int c = 0; c < NL_; c++) p[c] = 0.f;
    for (int e = t; e < H_; e += 256) {
        float x = g_cmp[row*H_ + e];
        #pragma unroll
        for (int c = 0; c < NL_; c++) p[c] = fmaf(x, W[e*NL_ + c], p[c]);
    }
    #pragma unroll
    for (int c = 0; c < NL_; c++) red[t][c] = p[c];
    __syncthreads();
    for (int st = 128; st > 0; st >>= 1) {
        if (t < st)
            #pragma unroll
            for (int c = 0; c < NL_; c++) red[t][c] += red[t+st][c];
        __syncthreads();
    }
    if (t == 0) {
        float l[NL_], mx = -1e30f, sum = 0.f;
        #pragma unroll
        for (int c = 0; c < NL_; c++) { l[c] = red[0][c] + bias[c]; mx = fmaxf(mx, l[c]); }
        #pragma unroll
        for (int c = 0; c < NL_; c++) { l[c] = expf(l[c] - mx); sum += l[c]; }
        float inv = 1.0f / sum;
        #pragma unroll
        for (int c = 0; c < NL_; c++) outp[row*NL_ + c] = l[c] * inv;
    }
}

// ---------------- launch --------------------------------------------------
extern "C" void kernel_launch(void* const* d_in, const int* in_sizes, int n_in,
                              void* d_out, int out_size)
{
    const int*   ids   = (const int*)  d_in[0];
    const int*   mask  = (const int*)  d_in[1];
    const int*   types = (const int*)  d_in[2];
    const int*   valid = (const int*)  d_in[3];
    const float* we    = (const float*)d_in[4];
    const float* pe    = (const float*)d_in[5];
    const float* te    = (const float*)d_in[6];
    const float* elg   = (const float*)d_in[7];
    const float* elb   = (const float*)d_in[8];
    const float* Wq    = (const float*)d_in[9];
    const float* bq    = (const float*)d_in[10];
    const float* Wk    = (const float*)d_in[11];
    const float* bk    = (const float*)d_in[12];
    const float* Wv    = (const float*)d_in[13];
    const float* bv    = (const float*)d_in[14];
    const float* Wo    = (const float*)d_in[15];
    const float* bo    = (const float*)d_in[16];
    const float* l1g   = (const float*)d_in[17];
    const float* l1b   = (const float*)d_in[18];
    const float* Wi    = (const float*)d_in[19];
    const float* bi    = (const float*)d_in[20];
    const float* Wo2   = (const float*)d_in[21];
    const float* bo2   = (const float*)d_in[22];
    const float* l2g   = (const float*)d_in[23];
    const float* l2b   = (const float*)d_in[24];
    const float* cW    = (const float*)d_in[25];
    const float* cb    = (const float*)d_in[26];
    float* outp = (float*)d_out;

    float *ph, *ptmp;
    __half *phh, *pqh, *pkh, *pvh, *pctxh, *pffh;
    __half *tq, *tk, *tv, *to, *ti, *to2;
    cudaGetSymbolAddress((void**)&ph,    g_h);
    cudaGetSymbolAddress((void**)&phh,   g_hh);
    cudaGetSymbolAddress((void**)&pqh,   g_qh);
    cudaGetSymbolAddress((void**)&pkh,   g_kh);
    cudaGetSymbolAddress((void**)&pvh,   g_vh);
    cudaGetSymbolAddress((void**)&pctxh, g_ctxh);
    cudaGetSymbolAddress((void**)&ptmp,  g_tmp);
    cudaGetSymbolAddress((void**)&pffh,  g_ffh);
    cudaGetSymbolAddress((void**)&tq,    g_tWq);
    cudaGetSymbolAddress((void**)&tk,    g_tWk);
    cudaGetSymbolAddress((void**)&tv,    g_tWv);
    cudaGetSymbolAddress((void**)&to,    g_tWo);
    cudaGetSymbolAddress((void**)&ti,    g_tWi);
    cudaGetSymbolAddress((void**)&to2,   g_tWo2);

    cudaFuncSetAttribute(attn_h,
                         cudaFuncAttributeMaxDynamicSharedMemorySize, AT_SMEM);

    const int smem32  = 2 * (32*HST  + 128*HST) * 2;   // 46,080 B
    const int smem128 = 2 * (128*HST + 128*HST) * 2;   // 73,728 B
    cudaFuncSetAttribute((const void*)gemm_h<32,1>,
                         cudaFuncAttributeMaxDynamicSharedMemorySize, smem32);
    cudaFuncSetAttribute((const void*)gemm_h<128,4>,
                         cudaFuncAttributeMaxDynamicSharedMemorySize, smem128);

    dim3 gQKV(H_ / 128,  M_ / 128, 3);   // (6, 16, 3) = 288 blocks, BM=128
    dim3 gH  (H_ / 128,  M_ / 32, 1);    // (6, 64) = 384 blocks, BM=32
    dim3 gFF (FF_ / 128, M_ / 128, 1);   // (24, 16) = 384 blocks, BM=128

    embed_kernel<<<M_, 256>>>(ids, types, we, pe, te, elg, elb);
    bias_kernel<<<(M_ + 255)/256, 256>>>(mask);
    cvtT_kernel<<<dim3(H_/32,  H_/32, L_), 256>>>(Wq,  tq,  H_,  H_);
    cvtT_kernel<<<dim3(H_/32,  H_/32, L_), 256>>>(Wk,  tk,  H_,  H_);
    cvtT_kernel<<<dim3(H_/32,  H_/32, L_), 256>>>(Wv,  tv,  H_,  H_);

    for (int l = 0; l < L_; l++) {
        const __half* wq = tq  + (size_t)l*H_*H_;
        const __half* wk = tk  + (size_t)l*H_*H_;
        const __half* wv = tv  + (size_t)l*H_*H_;
        const __half* wo = to  + (size_t)l*H_*H_;
        const __half* wi = ti  + (size_t)l*H_*FF_;
        const __half* w2 = to2 + (size_t)l*FF_*H_;

        gemm_h<128,4><<<gQKV, 256, smem128>>>(phh, wq, wk, wv,
                                bq + l*H_, bk + l*H_, bv + l*H_,
                                nullptr, nullptr, nullptr,
                                pqh, pkh, pvh, nullptr, M_, H_, H_, 0);

        if (l == 0) {
            cvtT_kernel<<<dim3(H_/32,  H_/32, L_), 256>>>(Wo,  to,  H_,  H_);
            cvtT_kernel<<<dim3(FF_/32, H_/32, L_), 256>>>(Wi,  ti,  H_,  FF_);
            cvtT_kernel<<<dim3(H_/32,  FF_/32, L_), 256>>>(Wo2, to2, FF_, H_);
        }

        attn_h<<<dim3(S_/64, NH_, B_), 256, AT_SMEM>>>();

        gemm_h<32,1><<<gH, 256, smem32>>>(pctxh, wo, wo, wo,
                              bo + l*H_, bo + l*H_, bo + l*H_,
                              ptmp, ptmp, ptmp,
                              nullptr, nullptr, nullptr, ph, M_, H_, H_, 0);
        ln_kernel<<<M_, 256>>>(ptmp, l1g + l*H_, l1b + l*H_, ph, phh);

        gemm_h<128,4><<<gFF, 256, smem128>>>(phh, wi, wi, wi,
                               bi + l*FF_, bi + l*FF_, bi + l*FF_,
                               nullptr, nullptr, nullptr,
                               pffh, pffh, pffh, nullptr, M_, FF_, H_, 1);
        gemm_h<32,1><<<gH, 256, smem32>>>(pffh, w2, w2, w2,
                              bo2 + l*H_, bo2 + l*H_, bo2 + l*H_,
                              ptmp, ptmp, ptmp,
                              nullptr, nullptr, nullptr, ph, M_, H_, FF_, 0);
        ln_kernel<<<M_, 256>>>(ptmp, l2g + l*H_, l2b + l*H_, ph, phh);
    }

    order_kernel<<<B_, 256>>>(valid);
    compact_kernel<<<M_, 256>>>();
    clf_kernel<<<M_, 256>>>(cW, cb, outp);
}

// round 15
// speedup vs baseline: 1.0199x; 1.0199x over previous
#include <cuda_runtime.h>
#include <cuda_fp16.h>
#include <math.h>

#define B_  8
#define S_  256
#define H_  768
#define L_  12
#define NH_ 12
#define D_  64
#define FF_ 3072
#define NL_ 9
#define M_  (B_*S_)   // 2048 token rows

// ---------------- scratch (device globals: allowed, no allocations) ---------
__device__ float  g_h  [M_*H_];    // fp32 residual stream
__device__ __half g_hh [M_*H_];    // fp16 copy (GEMM A operand)
__device__ __half g_qh [M_*H_];    // fp16 q/k/v (attention inputs)
__device__ __half g_kh [M_*H_];
__device__ __half g_vh [M_*H_];
__device__ __half g_ctxh[M_*H_];   // fp16 attn context (O-proj A operand)
__device__ float  g_tmp[M_*H_];
__device__ __half g_ffh[M_*FF_];   // fp16 FFN1 output (FFN2 A operand)
__device__ float  g_cmp[M_*H_];
__device__ float  g_bias[M_];
__device__ int    g_order[M_];

// fp16 weights, TRANSPOSED to [N][K] per layer (converted once per launch)
__device__ __half g_tWq [L_*H_*H_];
__device__ __half g_tWk [L_*H_*H_];
__device__ __half g_tWv [L_*H_*H_];
__device__ __half g_tWo [L_*H_*H_];
__device__ __half g_tWi [L_*H_*FF_];
__device__ __half g_tWo2[L_*FF_*H_];

// ---------------- helpers ------------------------------------------------
#define MMA_F16(acc, a, b)                                                   \
    asm volatile(                                                            \
        "mma.sync.aligned.m16n8k16.row.col.f32.f16.f16.f32 "                 \
        "{%0,%1,%2,%3},{%4,%5,%6,%7},{%8,%9},{%0,%1,%2,%3};\n"               \
        : "+f"(acc[0]), "+f"(acc[1]), "+f"(acc[2]), "+f"(acc[3])             \
        : "r"(a[0]), "r"(a[1]), "r"(a[2]), "r"(a[3]), "r"(b[0]), "r"(b[1]))

#define LDSM4(r, addr)                                                       \
    asm volatile(                                                            \
        "ldmatrix.sync.aligned.m8n8.x4.shared.b16 {%0,%1,%2,%3}, [%4];"      \
        : "=r"((r)[0]), "=r"((r)[1]), "=r"((r)[2]), "=r"((r)[3])             \
        : "r"(addr))

__device__ __forceinline__ void cp16(void* smem, const void* g) {
    unsigned s = (unsigned)__cvta_generic_to_shared(smem);
    asm volatile("cp.async.cg.shared.global [%0], [%1], 16;\n" :: "r"(s), "l"(g));
}
__device__ __forceinline__ void cp_commit() {
    asm volatile("cp.async.commit_group;\n");
}
template<int N> __device__ __forceinline__ void cp_wait() {
    asm volatile("cp.async.wait_group %0;\n" :: "n"(N));
}

// ---------------- weight fp16 convert + transpose ----------------------------
__global__ __launch_bounds__(256) void cvtT_kernel(
    const float* __restrict__ in, __half* __restrict__ out, int K, int N)
{
    __shared__ __half sm[32][33];
    const float* inL  = in  + (size_t)blockIdx.z * K * N;
    __half*      outL = out + (size_t)blockIdx.z * K * N;
    const int n0 = blockIdx.x * 32, k0 = blockIdx.y * 32;
    const int tid = threadIdx.x;

    #pragma unroll
    for (int i = 0; i < 4; i++) {
        int idx = tid + i*256;
        int k = idx >> 5, n = idx & 31;
        sm[n][k] = __float2half(inL[(size_t)(k0 + k) * N + n0 + n]);
    }
    __syncthreads();

    if (tid < 128) {
        int n  = tid >> 2;
        int k8 = (tid & 3) << 3;
        __half v[8];
        #pragma unroll
        for (int j = 0; j < 8; j++) v[j] = sm[n][k8 + j];
        *(uint4*)&outL[(size_t)(n0 + n) * K + k0 + k8] = *(uint4*)v;
    }
}

// ---------------- fused (sum, sumsq) block reduce (256 thr) ------------------
__device__ __forceinline__ void block_sum2(float a, float b, float* ws, int t,
                                           float& outa, float& outb) {
    #pragma unroll
    for (int o = 16; o > 0; o >>= 1) {
        a += __shfl_xor_sync(0xffffffffu, a, o);
        b += __shfl_xor_sync(0xffffffffu, b, o);
    }
    if ((t & 31) == 0) { ws[t >> 5] = a; ws[8 + (t >> 5)] = b; }
    __syncthreads();
    float ta = 0.f, tb = 0.f;
    #pragma unroll
    for (int w = 0; w < 8; w++) { ta += ws[w]; tb += ws[8 + w]; }
    outa = ta; outb = tb;
}

// ---------------- embeddings + LayerNorm (dual write fp32+fp16) -------------
__global__ __launch_bounds__(256) void embed_kernel(
    const int* __restrict__ ids, const int* __restrict__ types,
    const float* __restrict__ we, const float* __restrict__ pe,
    const float* __restrict__ te,
    const float* __restrict__ g, const float* __restrict__ bta)
{
    int row = blockIdx.x;
    int s   = row % S_;
    int t   = threadIdx.x;
    __shared__ float ws[16];

    int id = ids[row];
    int ty = types[row];
    float x0 = we[id*H_ + t]       + pe[s*H_ + t]       + te[ty*H_ + t];
    float x1 = we[id*H_ + t + 256] + pe[s*H_ + t + 256] + te[ty*H_ + t + 256];
    float x2 = we[id*H_ + t + 512] + pe[s*H_ + t + 512] + te[ty*H_ + t + 512];

    float ts, ts2;
    block_sum2(x0 + x1 + x2, x0*x0 + x1*x1 + x2*x2, ws, t, ts, ts2);
    float mean = ts * (1.0f / H_);
    float var  = ts2 * (1.0f / H_) - mean * mean;
    float rstd = rsqrtf(var + 1e-12f);

    float o0 = (x0 - mean)*rstd*g[t]     + bta[t];
    float o1 = (x1 - mean)*rstd*g[t+256] + bta[t+256];
    float o2 = (x2 - mean)*rstd*g[t+512] + bta[t+512];
    g_h [row*H_ + t]       = o0;  g_hh[row*H_ + t]       = __float2half(o0);
    g_h [row*H_ + t + 256] = o1;  g_hh[row*H_ + t + 256] = __float2half(o1);
    g_h [row*H_ + t + 512] = o2;  g_hh[row*H_ + t + 512] = __float2half(o2);
}

// ---------------- generic LayerNorm (dual write) ------------------------------
__global__ __launch_bounds__(256) void ln_kernel(
    const float* __restrict__ in, const float* __restrict__ g,
    const float* __restrict__ bta, float* __restrict__ outf,
    __half* __restrict__ outh)
{
    int row = blockIdx.x, t = threadIdx.x;
    __shared__ float ws[16];
    const float* xr = in + row*H_;
    float x0 = xr[t], x1 = xr[t + 256], x2 = xr[t + 512];

    float ts, ts2;
    block_sum2(x0 + x1 + x2, x0*x0 + x1*x1 + x2*x2, ws, t, ts, ts2);
    float mean = ts * (1.0f / H_);
    float var  = ts2 * (1.0f / H_) - mean * mean;
    float rstd = rsqrtf(var + 1e-12f);

    float o0 = (x0 - mean)*rstd*g[t]     + bta[t];
    float o1 = (x1 - mean)*rstd*g[t+256] + bta[t+256];
    float o2 = (x2 - mean)*rstd*g[t+512] + bta[t+512];
    outf[row*H_ + t]       = o0;  outh[row*H_ + t]       = __float2half(o0);
    outf[row*H_ + t + 256] = o1;  outh[row*H_ + t + 256] = __float2half(o1);
    outf[row*H_ + t + 512] = o2;  outh[row*H_ + t + 512] = __float2half(o2);
}

// ---------------- attention mask bias ----------------------------------------
__global__ void bias_kernel(const int* __restrict__ mask)
{
    int i = blockIdx.x * 256 + threadIdx.x;
    if (i < M_) g_bias[i] = (1.0f - (float)mask[i]) * -1e4f;
}

// ---------------- fp16 cp.async 3-stage GEMM, ldmatrix fragments -------------
#define HST 72   // smem row stride in halves (144 B; 16B-aligned rows)

template<int BM, int MT>
__global__ __launch_bounds__(256, 2) void gemm_h(
    const __half* __restrict__ A,
    const __half* __restrict__ W0, const __half* __restrict__ W1, const __half* __restrict__ W2,
    const float* __restrict__ bi0, const float* __restrict__ bi1, const float* __restrict__ bi2,
    float* __restrict__ Cf0, float* __restrict__ Cf1, float* __restrict__ Cf2,
    __half* __restrict__ Ch0, __half* __restrict__ Ch1, __half* __restrict__ Ch2,
    const float* __restrict__ res, int M, int N, int K, int act)
{
    const __half* Bt   = (blockIdx.z == 0) ? W0 : (blockIdx.z == 1 ? W1 : W2);
    const float*  bias = (blockIdx.z == 0) ? bi0 : (blockIdx.z == 1 ? bi1 : bi2);
    float*        Cf   = (blockIdx.z == 0) ? Cf0 : (blockIdx.z == 1 ? Cf1 : Cf2);
    __half*       Ch   = (blockIdx.z == 0) ? Ch0 : (blockIdx.z == 1 ? Ch1 : Ch2);

    constexpr int ASZ = BM  * HST;
    constexpr int BSZ = 128 * HST;
    constexpr int SSZ = ASZ + BSZ;       // halves per stage
    extern __shared__ __half smh[];

    const int tid  = threadIdx.x;
    const int row0 = blockIdx.y * BM;
    const int col0 = blockIdx.x * 128;

    const int warp = tid >> 5, lane = tid & 31;
    const int wm = warp >> 2, wn = warp & 3;
    const int grp = lane >> 2, tg = lane & 3;

    const int lrowA = lane & 15;
    const int lcolA = (lane >> 4) * 8;
    const int lrowB = (lane & 7) + ((lane >> 4) & 1) * 8;
    const int lcolB = ((lane >> 3) & 1) * 8;

    const unsigned smemBase = (unsigned)__cvta_generic_to_shared(smh);
    unsigned offA[MT], offB[2];
    #pragma unroll
    for (int mt = 0; mt < MT; mt++)
        offA[mt] = (unsigned)(((wm*(BM/2) + mt*16 + lrowA)*HST + lcolA) * 2);
    #pragma unroll
    for (int p = 0; p < 2; p++)
        offB[p] = (unsigned)(((wn*32 + p*16 + lrowB)*HST + lcolB) * 2 + ASZ*2);

    float acc[MT][4][4];
    #pragma unroll
    for (int mt = 0; mt < MT; mt++)
        #pragma unroll
        for (int nt = 0; nt < 4; nt++)
            #pragma unroll
            for (int c = 0; c < 4; c++) acc[mt][nt][c] = 0.f;

    const __half* Ag = A  + (size_t)row0 * K;
    const __half* Bg = Bt + (size_t)col0 * K;

    auto issue = [&](int it, int stg) {
        __half* As = smh + stg * SSZ;
        __half* Bs = As + ASZ;
        const int kk = it * 64;
        #pragma unroll
        for (int p = 0; p < BM*8/256; p++) {
            int idx = tid + p*256;
            int r = idx >> 3, c8 = (idx & 7) << 3;
            cp16(&As[r*HST + c8], Ag + (size_t)r*K + kk + c8);
        }
        #pragma unroll
        for (int p = 0; p < 4; p++) {
            int idx = tid + p*256;
            int n = idx >> 3, c8 = (idx & 7) << 3;
            cp16(&Bs[n*HST + c8], Bg + (size_t)n*K + kk + c8);
        }
        cp_commit();
    };

    const int nIter = K >> 6;
    issue(0, 0);
    issue(1, 1);

    int stg = 0;
    for (int it = 0; it < nIter; it++) {
        if (it + 1 < nIter) cp_wait<1>(); else cp_wait<0>();
        __syncthreads();                       // all reads of stage (it-1)%3 done
        if (it + 2 < nIter) {
            int ns = stg + 2; if (ns >= 3) ns -= 3;
            issue(it + 2, ns);                 // overwrites stage (it-1)%3
        }

        const unsigned bufBase = smemBase + (unsigned)(stg * SSZ * 2);

        #pragma unroll
        for (int ks = 0; ks < 4; ks++) {
            const unsigned kb = (unsigned)(ks * 32);
            unsigned af[MT][4], bf0[4], bf1[4];
            #pragma unroll
            for (int mt = 0; mt < MT; mt++)
                LDSM4(af[mt], bufBase + offA[mt] + kb);
            LDSM4(bf0, bufBase + offB[0] + kb);
            LDSM4(bf1, bufBase + offB[1] + kb);
            #pragma unroll
            for (int mt = 0; mt < MT; mt++) {
                MMA_F16(acc[mt][0], af[mt], (bf0 + 0));
                MMA_F16(acc[mt][1], af[mt], (bf0 + 2));
                MMA_F16(acc[mt][2], af[mt], (bf1 + 0));
                MMA_F16(acc[mt][3], af[mt], (bf1 + 2));
            }
        }
        if (++stg == 3) stg = 0;
    }

    #pragma unroll
    for (int mt = 0; mt < MT; mt++) {
        #pragma unroll
        for (int nt = 0; nt < 4; nt++) {
            int r0 = row0 + wm*(BM/2) + mt*16 + grp;
            int r1 = r0 + 8;
            int c  = col0 + wn*32 + nt*8 + 2*tg;
            float b0 = bias[c], b1 = bias[c+1];
            float v00 = acc[mt][nt][0] + b0, v01 = acc[mt][nt][1] + b1;
            float v10 = acc[mt][nt][2] + b0, v11 = acc[mt][nt][3] + b1;
            if (res) {
                v00 += res[(size_t)r0*N + c];     v01 += res[(size_t)r0*N + c + 1];
                v10 += res[(size_t)r1*N + c];     v11 += res[(size_t)r1*N + c + 1];
            }
            if (act) {
                v00 = 0.5f*v00*(1.0f + erff(v00*0.70710678118654752f));
                v01 = 0.5f*v01*(1.0f + erff(v01*0.70710678118654752f));
                v10 = 0.5f*v10*(1.0f + erff(v10*0.70710678118654752f));
                v11 = 0.5f*v11*(1.0f + erff(v11*0.70710678118654752f));
            }
            if (Cf) {
                *(float2*)&Cf[(size_t)r0*N + c] = make_float2(v00, v01);
                *(float2*)&Cf[(size_t)r1*N + c] = make_float2(v10, v11);
            }
            if (Ch) {
                *(__half2*)&Ch[(size_t)r0*N + c] = __floats2half2_rn(v00, v01);
                *(__half2*)&Ch[(size_t)r1*N + c] = __floats2half2_rn(v10, v11);
            }
        }
    }
}

// ---------------- fp16 fused attention (phase-1 LDSM, phase-2 scalar) --------
#define AT_KOFF 0
#define AT_QOFF (256*72)
#define AT_VOFF (256*72 + 64*72)
#define AT_FOFF (AT_VOFF + 64*264)
#define AT_SMEM (AT_FOFF*2 + (256 + 256 + 256)*4)

__global__ __launch_bounds__(256, 2) void attn_h()
{
    const int qt = blockIdx.x, h = blockIdx.y, b = blockIdx.z;
    const int q0 = qt * 64;
    const int tid = threadIdx.x;
    const int warp = tid >> 5, lane = tid & 31;
    const int grp = lane >> 2, tg = lane & 3;
    const int wm = warp >> 2, wn = warp & 3;

    extern __shared__ __half smh[];
    __half* Ks = smh + AT_KOFF;
    __half* Qs = smh + AT_QOFF;
    __half* Vt = smh + AT_VOFF;
    __half* Ps = smh;
    float* fb     = (float*)(smh + AT_FOFF);
    float* bias_s = fb;
    float* pmax   = fb + 256;
    float* psum   = fb + 512;

    const __half* Kg = g_kh + (size_t)(b*S_)*H_ + h*D_;
    #pragma unroll
    for (int i = 0; i < 8; i++) {
        int idx = i*256 + tid;
        int r = idx >> 3, c = (idx & 7) << 3;
        cp16(&Ks[r*72 + c], Kg + (size_t)r*H_ + c);
    }
    const __half* Qg = g_qh + (size_t)(b*S_ + q0)*H_ + h*D_;
    #pragma unroll
    for (int i = 0; i < 2; i++) {
        int idx = i*256 + tid;
        int r = idx >> 3, c = (idx & 7) << 3;
        cp16(&Qs[r*72 + c], Qg + (size_t)r*H_ + c);
    }
    cp_commit();

    const __half* Vg = g_vh + (size_t)(b*S_)*H_ + h*D_;
    #pragma unroll
    for (int i = 0; i < 8; i++) {
        int idx = i*256 + tid;
        int k = idx >> 3, d = (idx & 7) << 3;
        uint4 v = *(const uint4*)(Vg + (size_t)k*H_ + d);
        __half hv[8];
        *(uint4*)hv = v;
        #pragma unroll
        for (int j = 0; j < 8; j++) Vt[(d+j)*264 + k] = hv[j];
    }
    bias_s[tid] = g_bias[b*S_ + tid];
    cp_wait<0>();
    __syncthreads();

    // ---- phase 1: scores = Q @ K^T (ldmatrix fragments, verified stride-72) --
    float acc1[2][8][4];
    #pragma unroll
    for (int mt = 0; mt < 2; mt++)
        #pragma unroll
        for (int nt = 0; nt < 8; nt++)
            #pragma unroll
            for (int c = 0; c < 4; c++) acc1[mt][nt][c] = 0.f;

    {
        const int lrowA = lane & 15;
        const int lcolA = (lane >> 4) * 8;
        const int lrowB = (lane & 7) + ((lane >> 4) & 1) * 8;
        const int lcolB = ((lane >> 3) & 1) * 8;
        const unsigned smemBase = (unsigned)__cvta_generic_to_shared(smh);

        unsigned offQ[2], offK[4];
        #pragma unroll
        for (int mt = 0; mt < 2; mt++)
            offQ[mt] = (unsigned)(AT_QOFF*2 + ((wm*32 + mt*16 + lrowA)*72 + lcolA)*2);
        #pragma unroll
        for (int p = 0; p < 4; p++)
            offK[p] = (unsigned)(((wn*64 + p*16 + lrowB)*72 + lcolB)*2);

        #pragma unroll
        for (int ks = 0; ks < 4; ks++) {
            const unsigned kb = (unsigned)(ks * 32);
            unsigned af[2][4], bf[4][4];
            #pragma unroll
            for (int mt = 0; mt < 2; mt++)
                LDSM4(af[mt], smemBase + offQ[mt] + kb);
            #pragma unroll
            for (int p = 0; p < 4; p++)
                LDSM4(bf[p], smemBase + offK[p] + kb);
            #pragma unroll
            for (int mt = 0; mt < 2; mt++)
                #pragma unroll
                for (int p = 0; p < 4; p++) {
                    MMA_F16(acc1[mt][p*2],   af[mt], (bf[p] + 0));
                    MMA_F16(acc1[mt][p*2+1], af[mt], (bf[p] + 2));
                }
        }
    }

    // ---- scale + bias in regs; row max via shfl + smem ----
    float rmax[2][2];
    #pragma unroll
    for (int mt = 0; mt < 2; mt++) { rmax[mt][0] = -1e30f; rmax[mt][1] = -1e30f; }
    #pragma unroll
    for (int mt = 0; mt < 2; mt++)
        #pragma unroll
        for (int p = 0; p < 4; p++)
            #pragma unroll
            for (int q = 0; q < 2; q++) {
                int nt = p*2 + q;
                int c = wn*64 + p*16 + q*8 + 2*tg;
                float b0 = bias_s[c], b1 = bias_s[c+1];
                acc1[mt][nt][0] = acc1[mt][nt][0]*0.125f + b0;
                acc1[mt][nt][1] = acc1[mt][nt][1]*0.125f + b1;
                acc1[mt][nt][2] = acc1[mt][nt][2]*0.125f + b0;
                acc1[mt][nt][3] = acc1[mt][nt][3]*0.125f + b1;
                rmax[mt][0] = fmaxf(rmax[mt][0], fmaxf(acc1[mt][nt][0], acc1[mt][nt][1]));
                rmax[mt][1] = fmaxf(rmax[mt][1], fmaxf(acc1[mt][nt][2], acc1[mt][nt][3]));
            }
    #pragma unroll
    for (int mt = 0; mt < 2; mt++)
        #pragma unroll
        for (int hh = 0; hh < 2; hh++) {
            float m = rmax[mt][hh];
            m = fmaxf(m, __shfl_xor_sync(0xffffffffu, m, 1));
            m = fmaxf(m, __shfl_xor_sync(0xffffffffu, m, 2));
            rmax[mt][hh] = m;
        }
    if (tg == 0) {
        #pragma unroll
        for (int mt = 0; mt < 2; mt++) {
            pmax[(wm*32 + mt*16 + grp)*4 + wn]     = rmax[mt][0];
            pmax[(wm*32 + mt*16 + grp + 8)*4 + wn] = rmax[mt][1];
        }
    }
    __syncthreads();   // gates: all K reads done -> Ps alias writable

    // ---- exp (regs), write fp16 P, partial sums ----
    float rsum[2][2] = {{0.f,0.f},{0.f,0.f}};
    #pragma unroll
    for (int mt = 0; mt < 2; mt++) {
        int lr0 = wm*32 + mt*16 + grp, lr1 = lr0 + 8;
        float m0 = fmaxf(fmaxf(pmax[lr0*4+0], pmax[lr0*4+1]), fmaxf(pmax[lr0*4+2], pmax[lr0*4+3]));
        float m1 = fmaxf(fmaxf(pmax[lr1*4+0], pmax[lr1*4+1]), fmaxf(pmax[lr1*4+2], pmax[lr1*4+3]));
        #pragma unroll
        for (int p = 0; p < 4; p++)
            #pragma unroll
            for (int q = 0; q < 2; q++) {
                int nt = p*2 + q;
                int c = wn*64 + p*16 + q*8 + 2*tg;
                float e0 = __expf(acc1[mt][nt][0] - m0);
                float e1 = __expf(acc1[mt][nt][1] - m0);
                float e2 = __expf(acc1[mt][nt][2] - m1);
                float e3 = __expf(acc1[mt][nt][3] - m1);
                rsum[mt][0] += e0 + e1;
                rsum[mt][1] += e2 + e3;
                *(__half2*)&Ps[lr0*264 + c] = __floats2half2_rn(e0, e1);
                *(__half2*)&Ps[lr1*264 + c] = __floats2half2_rn(e2, e3);
            }
    }
    #pragma unroll
    for (int mt = 0; mt < 2; mt++)
        #pragma unroll
        for (int hh = 0; hh < 2; hh++) {
            float s = rsum[mt][hh];
            s += __shfl_xor_sync(0xffffffffu, s, 1);
            s += __shfl_xor_sync(0xffffffffu, s, 2);
            rsum[mt][hh] = s;
        }
    if (tg == 0) {
        #pragma unroll
        for (int mt = 0; mt < 2; mt++) {
            psum[(wm*32 + mt*16 + grp)*4 + wn]     = rsum[mt][0];
            psum[(wm*32 + mt*16 + grp + 8)*4 + wn] = rsum[mt][1];
        }
    }
    __syncthreads();

    // ---- phase 2: ctx = P @ V (scalar fragment loads; stride-264 quarantined)
    float acc2[2][2][4];
    #pragma unroll
    for (int mt = 0; mt < 2; mt++)
        #pragma unroll
        for (int nt = 0; nt < 2; nt++)
            #pragma unroll
            for (int c = 0; c < 4; c++) acc2[mt][nt][c] = 0.f;

    {
        const unsigned* Pw = (const unsigned*)Ps;
        const unsigned* Vw = (const unsigned*)Vt;
        #pragma unroll 4
        for (int ks = 0; ks < 16; ks++) {
            const int kw = ks * 8;
            unsigned af[2][4], bf[2][2];
            #pragma unroll
            for (int mt = 0; mt < 2; mt++) {
                const unsigned* Ar = Pw + (wm*32 + mt*16 + grp)*132;
                af[mt][0] = Ar[kw + tg];
                af[mt][1] = Ar[8*132 + kw + tg];
                af[mt][2] = Ar[kw + tg + 4];
                af[mt][3] = Ar[8*132 + kw + tg + 4];
            }
            #pragma unroll
            for (int nt = 0; nt < 2; nt++) {
                const unsigned* Br = Vw + (wn*16 + nt*8 + grp)*132;
                bf[nt][0] = Br[kw + tg];
                bf[nt][1] = Br[kw + tg + 4];
            }
            #pragma unroll
            for (int mt = 0; mt < 2; mt++)
                #pragma unroll
                for (int nt = 0; nt < 2; nt++)
                    MMA_F16(acc2[mt][nt], af[mt], bf[nt]);
        }
    }

    #pragma unroll
    for (int mt = 0; mt < 2; mt++) {
        int lr0 = wm*32 + mt*16 + grp, lr1 = lr0 + 8;
        float i0 = 1.0f / (psum[lr0*4+0] + psum[lr0*4+1] + psum[lr0*4+2] + psum[lr0*4+3]);
        float i1 = 1.0f / (psum[lr1*4+0] + psum[lr1*4+1] + psum[lr1*4+2] + psum[lr1*4+3]);
        #pragma unroll
        for (int nt = 0; nt < 2; nt++) {
            int c = wn*16 + nt*8 + 2*tg;
            __half* o0 = g_ctxh + (size_t)(b*S_ + q0 + lr0)*H_ + h*D_ + c;
            __half* o1 = g_ctxh + (size_t)(b*S_ + q0 + lr1)*H_ + h*D_ + c;
            *(__half2*)o0 = __floats2half2_rn(acc2[mt][nt][0]*i0, acc2[mt][nt][1]*i0);
            *(__half2*)o1 = __floats2half2_rn(acc2[mt][nt][2]*i1, acc2[mt][nt][3]*i1);
        }
    }
}

// ---------------- stable compaction order per batch --------------------------
__global__ __launch_bounds__(256) void order_kernel(const int* __restrict__ valid)
{
    int b = blockIdx.x, t = threadIdx.x;
    __shared__ int sc[256];
    __shared__ int ord[256];
    int v = valid[b*S_ + t];
    sc[t] = v; __syncthreads();
    for (int off = 1; off < 256; off <<= 1) {
        int x = (t >= off) ? sc[t - off] : 0;
        __syncthreads();
        sc[t] += x;
        __syncthreads();
    }
    ord[t] = -1; __syncthreads();
    if (v) ord[sc[t] - v] = t;
    __syncthreads();
    g_order[b*S_ + t] = ord[t];
}

__global__ __launch_bounds__(256) void compact_kernel()
{
    int row = blockIdx.x;
    int b = row / S_;
    int src = g_order[row];
    int t = threadIdx.x;
    if (src < 0) {
        for (int e = t; e < H_; e += 256) g_cmp[row*H_ + e] = 0.f;
    } else {
        const float* xp = g_h + (b*S_ + src)*H_;
        for (int e = t; e < H_; e += 256) g_cmp[row*H_ + e] = xp[e];
    }
}

// ---------------- classifier + softmax ---------------------------------------
__global__ __launch_bounds__(256) void clf_kernel(
    const float* __restrict__ W, const float* __restrict__ bias,
    float* __restrict__ outp)
{
    int row = blockIdx.x, t = threadIdx.x;
    __shared__ float red[256][NL_ + 1];
    float p[NL_];
    #pragma unroll
    for (int c = 0; c < NL_; c++) p[c] = 0.f;
    for (int e = t; e < H_; e += 256) {
        float x = g_cmp[row*H_ + e];
        #pragma unroll
        for (int c = 0; c < NL_; c++) p[c] = fmaf(x, W[e*NL_ + c], p[c]);
    }
    #pragma unroll
    for (int c = 0; c < NL_; c++) red[t][c] = p[c];
    __syncthreads();
    for (int st = 128; st > 0; st >>= 1) {
        if (t < st)
            #pragma unroll
            for (int c = 0; c < NL_; c++) red[t][c] += red[t+st][c];
        __syncthreads();
    }
    if (t == 0) {
        float l[NL_], mx = -1e30f, sum = 0.f;
        #pragma unroll
        for (int c = 0; c < NL_; c++) { l[c] = red[0][c] + bias[c]; mx = fmaxf(mx, l[c]); }
        #pragma unroll
        for (int c = 0; c < NL_; c++) { l[c] = expf(l[c] - mx); sum += l[c]; }
        float inv = 1.0f / sum;
        #pragma unroll
        for (int c = 0; c < NL_; c++) outp[row*NL_ + c] = l[c] * inv;
    }
}

// ---------------- launch --------------------------------------------------
extern "C" void kernel_launch(void* const* d_in, const int* in_sizes, int n_in,
                              void* d_out, int out_size)
{
    const int*   ids   = (const int*)  d_in[0];
    const int*   mask  = (const int*)  d_in[1];
    const int*   types = (const int*)  d_in[2];
    const int*   valid = (const int*)  d_in[3];
    const float* we    = (const float*)d_in[4];
    const float* pe    = (const float*)d_in[5];
    const float* te    = (const float*)d_in[6];
    const float* elg   = (const float*)d_in[7];
    const float* elb   = (const float*)d_in[8];
    const float* Wq    = (const float*)d_in[9];
    const float* bq    = (const float*)d_in[10];
    const float* Wk    = (const float*)d_in[11];
    const float* bk    = (const float*)d_in[12];
    const float* Wv    = (const float*)d_in[13];
    const float* bv    = (const float*)d_in[14];
    const float* Wo    = (const float*)d_in[15];
    const float* bo    = (const float*)d_in[16];
    const float* l1g   = (const float*)d_in[17];
    const float* l1b   = (const float*)d_in[18];
    const float* Wi    = (const float*)d_in[19];
    const float* bi    = (const float*)d_in[20];
    const float* Wo2   = (const float*)d_in[21];
    const float* bo2   = (const float*)d_in[22];
    const float* l2g   = (const float*)d_in[23];
    const float* l2b   = (const float*)d_in[24];
    const float* cW    = (const float*)d_in[25];
    const float* cb    = (const float*)d_in[26];
    float* outp = (float*)d_out;

    float *ph, *ptmp;
    __half *phh, *pqh, *pkh, *pvh, *pctxh, *pffh;
    __half *tq, *tk, *tv, *to, *ti, *to2;
    cudaGetSymbolAddress((void**)&ph,    g_h);
    cudaGetSymbolAddress((void**)&phh,   g_hh);
    cudaGetSymbolAddress((void**)&pqh,   g_qh);
    cudaGetSymbolAddress((void**)&pkh,   g_kh);
    cudaGetSymbolAddress((void**)&pvh,   g_vh);
    cudaGetSymbolAddress((void**)&pctxh, g_ctxh);
    cudaGetSymbolAddress((void**)&ptmp,  g_tmp);
    cudaGetSymbolAddress((void**)&pffh,  g_ffh);
    cudaGetSymbolAddress((void**)&tq,    g_tWq);
    cudaGetSymbolAddress((void**)&tk,    g_tWk);
    cudaGetSymbolAddress((void**)&tv,    g_tWv);
    cudaGetSymbolAddress((void**)&to,    g_tWo);
    cudaGetSymbolAddress((void**)&ti,    g_tWi);
    cudaGetSymbolAddress((void**)&to2,   g_tWo2);

    cudaFuncSetAttribute(attn_h,
                         cudaFuncAttributeMaxDynamicSharedMemorySize, AT_SMEM);

    const int smem32  = 3 * (32*HST  + 128*HST) * 2;   // 69,120 B
    const int smem128 = 3 * (128*HST + 128*HST) * 2;   // 110,592 B
    cudaFuncSetAttribute((const void*)gemm_h<32,1>,
                         cudaFuncAttributeMaxDynamicSharedMemorySize, smem32);
    cudaFuncSetAttribute((const void*)gemm_h<128,4>,
                         cudaFuncAttributeMaxDynamicSharedMemorySize, smem128);

    dim3 gQKV(H_ / 128,  M_ / 128, 3);   // (6, 16, 3) = 288 blocks, BM=128
    dim3 gH  (H_ / 128,  M_ / 32, 1);    // (6, 64) = 384 blocks, BM=32
    dim3 gFF (FF_ / 128, M_ / 128, 1);   // (24, 16) = 384 blocks, BM=128

    embed_kernel<<<M_, 256>>>(ids, types, we, pe, te, elg, elb);
    bias_kernel<<<(M_ + 255)/256, 256>>>(mask);
    cvtT_kernel<<<dim3(H_/32,  H_/32, L_), 256>>>(Wq,  tq,  H_,  H_);
    cvtT_kernel<<<dim3(H_/32,  H_/32, L_), 256>>>(Wk,  tk,  H_,  H_);
    cvtT_kernel<<<dim3(H_/32,  H_/32, L_), 256>>>(Wv,  tv,  H_,  H_);

    for (int l = 0; l < L_; l++) {
        const __half* wq = tq  + (size_t)l*H_*H_;
        const __half* wk = tk  + (size_t)l*H_*H_;
        const __half* wv = tv  + (size_t)l*H_*H_;
        const __half* wo = to  + (size_t)l*H_*H_;
        const __half* wi = ti  + (size_t)l*H_*FF_;
        const __half* w2 = to2 + (size_t)l*FF_*H_;

        gemm_h<128,4><<<gQKV, 256, smem128>>>(phh, wq, wk, wv,
                                bq + l*H_, bk + l*H_, bv + l*H_,
                                nullptr, nullptr, nullptr,
                                pqh, pkh, pvh, nullptr, M_, H_, H_, 0);

        if (l == 0) {
            cvtT_kernel<<<dim3(H_/32,  H_/32, L_), 256>>>(Wo,  to,  H_,  H_);
            cvtT_kernel<<<dim3(FF_/32, H_/32, L_), 256>>>(Wi,  ti,  H_,  FF_);
            cvtT_kernel<<<dim3(H_/32,  FF_/32, L_), 256>>>(Wo2, to2, FF_, H_);
        }

        attn_h<<<dim3(S_/64, NH_, B_), 256, AT_SMEM>>>();

        gemm_h<32,1><<<gH, 256, smem32>>>(pctxh, wo, wo, wo,
                              bo + l*H_, bo + l*H_, bo + l*H_,
                              ptmp, ptmp, ptmp,
                              nullptr, nullptr, nullptr, ph, M_, H_, H_, 0);
        ln_kernel<<<M_, 256>>>(ptmp, l1g + l*H_, l1b + l*H_, ph, phh);

        gemm_h<128,4><<<gFF, 256, smem128>>>(phh, wi, wi, wi,
                               bi + l*FF_, bi + l*FF_, bi + l*FF_,
                               nullptr, nullptr, nullptr,
                               pffh, pffh, pffh, nullptr, M_, FF_, H_, 1);
        gemm_h<32,1><<<gH, 256, smem32>>>(pffh, w2, w2, w2,
                              bo2 + l*H_, bo2 + l*H_, bo2 + l*H_,
                              ptmp, ptmp, ptmp,
                              nullptr, nullptr, nullptr, ph, M_, H_, FF_, 0);
        ln_kernel<<<M_, 256>>>(ptmp, l2g + l*H_, l2b + l*H_, ph, phh);
    }

    order_kernel<<<B_, 256>>>(valid);
    compact_kernel<<<M_, 256>>>();
    clf_kernel<<<M_, 256>>>(cW, cb, outp);
}

// round 16
// speedup vs baseline: 1.0284x; 1.0084x over previous
#include <cuda_runtime.h>
#include <cuda_fp16.h>
#include <math.h>

#define B_  8
#define S_  256
#define H_  768
#define L_  12
#define NH_ 12
#define D_  64
#define FF_ 3072
#define NL_ 9
#define M_  (B_*S_)   // 2048 token rows

// ---------------- scratch (device globals: allowed, no allocations) ---------
__device__ float  g_h  [M_*H_];    // fp32 residual stream
__device__ __half g_hh [M_*H_];    // fp16 copy (GEMM A operand)
__device__ __half g_qh [M_*H_];    // fp16 q/k/v (attention inputs)
__device__ __half g_kh [M_*H_];
__device__ __half g_vh [M_*H_];
__device__ __half g_ctxh[M_*H_];   // fp16 attn context (O-proj A operand)
__device__ float  g_tmp[M_*H_];
__device__ __half g_ffh[M_*FF_];   // fp16 FFN1 output (FFN2 A operand)
__device__ float  g_cmp[M_*H_];
__device__ float  g_bias[M_];
__device__ int    g_order[M_];

// fp16 weights, TRANSPOSED to [N][K] per layer (converted once per launch)
__device__ __half g_tWq [L_*H_*H_];
__device__ __half g_tWk [L_*H_*H_];
__device__ __half g_tWv [L_*H_*H_];
__device__ __half g_tWo [L_*H_*H_];
__device__ __half g_tWi [L_*H_*FF_];
__device__ __half g_tWo2[L_*FF_*H_];

// ---------------- helpers ------------------------------------------------
#define MMA_F16(acc, a, b)                                                   \
    asm volatile(                                                            \
        "mma.sync.aligned.m16n8k16.row.col.f32.f16.f16.f32 "                 \
        "{%0,%1,%2,%3},{%4,%5,%6,%7},{%8,%9},{%0,%1,%2,%3};\n"               \
        : "+f"(acc[0]), "+f"(acc[1]), "+f"(acc[2]), "+f"(acc[3])             \
        : "r"(a[0]), "r"(a[1]), "r"(a[2]), "r"(a[3]), "r"(b[0]), "r"(b[1]))

#define LDSM4(r, addr)                                                       \
    asm volatile(                                                            \
        "ldmatrix.sync.aligned.m8n8.x4.shared.b16 {%0,%1,%2,%3}, [%4];"      \
        : "=r"((r)[0]), "=r"((r)[1]), "=r"((r)[2]), "=r"((r)[3])             \
        : "r"(addr))

__device__ __forceinline__ void cp16(void* smem, const void* g) {
    unsigned s = (unsigned)__cvta_generic_to_shared(smem);
    asm volatile("cp.async.cg.shared.global [%0], [%1], 16;\n" :: "r"(s), "l"(g));
}
__device__ __forceinline__ void cp_commit() {
    asm volatile("cp.async.commit_group;\n");
}
template<int N> __device__ __forceinline__ void cp_wait() {
    asm volatile("cp.async.wait_group %0;\n" :: "n"(N));
}

// ---------------- weight fp16 convert + transpose ----------------------------
__global__ __launch_bounds__(256) void cvtT_kernel(
    const float* __restrict__ in, __half* __restrict__ out, int K, int N)
{
    __shared__ __half sm[32][33];
    const float* inL  = in  + (size_t)blockIdx.z * K * N;
    __half*      outL = out + (size_t)blockIdx.z * K * N;
    const int n0 = blockIdx.x * 32, k0 = blockIdx.y * 32;
    const int tid = threadIdx.x;

    #pragma unroll
    for (int i = 0; i < 4; i++) {
        int idx = tid + i*256;
        int k = idx >> 5, n = idx & 31;
        sm[n][k] = __float2half(inL[(size_t)(k0 + k) * N + n0 + n]);
    }
    __syncthreads();

    if (tid < 128) {
        int n  = tid >> 2;
        int k8 = (tid & 3) << 3;
        __half v[8];
        #pragma unroll
        for (int j = 0; j < 8; j++) v[j] = sm[n][k8 + j];
        *(uint4*)&outL[(size_t)(n0 + n) * K + k0 + k8] = *(uint4*)v;
    }
}

// ---------------- fused (sum, sumsq) block reduce (256 thr) ------------------
__device__ __forceinline__ void block_sum2(float a, float b, float* ws, int t,
                                           float& outa, float& outb) {
    #pragma unroll
    for (int o = 16; o > 0; o >>= 1) {
        a += __shfl_xor_sync(0xffffffffu, a, o);
        b += __shfl_xor_sync(0xffffffffu, b, o);
    }
    if ((t & 31) == 0) { ws[t >> 5] = a; ws[8 + (t >> 5)] = b; }
    __syncthreads();
    float ta = 0.f, tb = 0.f;
    #pragma unroll
    for (int w = 0; w < 8; w++) { ta += ws[w]; tb += ws[8 + w]; }
    outa = ta; outb = tb;
}

// ---------------- embeddings + LayerNorm (dual write fp32+fp16) -------------
__global__ __launch_bounds__(256) void embed_kernel(
    const int* __restrict__ ids, const int* __restrict__ types,
    const float* __restrict__ we, const float* __restrict__ pe,
    const float* __restrict__ te,
    const float* __restrict__ g, const float* __restrict__ bta)
{
    int row = blockIdx.x;
    int s   = row % S_;
    int t   = threadIdx.x;
    __shared__ float ws[16];

    int id = ids[row];
    int ty = types[row];
    float x0 = we[id*H_ + t]       + pe[s*H_ + t]       + te[ty*H_ + t];
    float x1 = we[id*H_ + t + 256] + pe[s*H_ + t + 256] + te[ty*H_ + t + 256];
    float x2 = we[id*H_ + t + 512] + pe[s*H_ + t + 512] + te[ty*H_ + t + 512];

    float ts, ts2;
    block_sum2(x0 + x1 + x2, x0*x0 + x1*x1 + x2*x2, ws, t, ts, ts2);
    float mean = ts * (1.0f / H_);
    float var  = ts2 * (1.0f / H_) - mean * mean;
    float rstd = rsqrtf(var + 1e-12f);

    float o0 = (x0 - mean)*rstd*g[t]     + bta[t];
    float o1 = (x1 - mean)*rstd*g[t+256] + bta[t+256];
    float o2 = (x2 - mean)*rstd*g[t+512] + bta[t+512];
    g_h [row*H_ + t]       = o0;  g_hh[row*H_ + t]       = __float2half(o0);
    g_h [row*H_ + t + 256] = o1;  g_hh[row*H_ + t + 256] = __float2half(o1);
    g_h [row*H_ + t + 512] = o2;  g_hh[row*H_ + t + 512] = __float2half(o2);
}

// ---------------- generic LayerNorm (dual write) ------------------------------
__global__ __launch_bounds__(256) void ln_kernel(
    const float* __restrict__ in, const float* __restrict__ g,
    const float* __restrict__ bta, float* __restrict__ outf,
    __half* __restrict__ outh)
{
    int row = blockIdx.x, t = threadIdx.x;
    __shared__ float ws[16];
    const float* xr = in + row*H_;
    float x0 = xr[t], x1 = xr[t + 256], x2 = xr[t + 512];

    float ts, ts2;
    block_sum2(x0 + x1 + x2, x0*x0 + x1*x1 + x2*x2, ws, t, ts, ts2);
    float mean = ts * (1.0f / H_);
    float var  = ts2 * (1.0f / H_) - mean * mean;
    float rstd = rsqrtf(var + 1e-12f);

    float o0 = (x0 - mean)*rstd*g[t]     + bta[t];
    float o1 = (x1 - mean)*rstd*g[t+256] + bta[t+256];
    float o2 = (x2 - mean)*rstd*g[t+512] + bta[t+512];
    outf[row*H_ + t]       = o0;  outh[row*H_ + t]       = __float2half(o0);
    outf[row*H_ + t + 256] = o1;  outh[row*H_ + t + 256] = __float2half(o1);
    outf[row*H_ + t + 512] = o2;  outh[row*H_ + t + 512] = __float2half(o2);
}

// ---------------- attention mask bias ----------------------------------------
__global__ void bias_kernel(const int* __restrict__ mask)
{
    int i = blockIdx.x * 256 + threadIdx.x;
    if (i < M_) g_bias[i] = (1.0f - (float)mask[i]) * -1e4f;
}

// ---------------- fp16 cp.async 3-stage GEMM, ldmatrix fragments -------------
#define HST 72   // smem row stride in halves (144 B; 16B-aligned rows)

template<int BM, int MT, int MINB>
__global__ __launch_bounds__(256, MINB) void gemm_h(
    const __half* __restrict__ A,
    const __half* __restrict__ W0, const __half* __restrict__ W1, const __half* __restrict__ W2,
    const float* __restrict__ bi0, const float* __restrict__ bi1, const float* __restrict__ bi2,
    float* __restrict__ Cf0, float* __restrict__ Cf1, float* __restrict__ Cf2,
    __half* __restrict__ Ch0, __half* __restrict__ Ch1, __half* __restrict__ Ch2,
    const float* __restrict__ res, int M, int N, int K, int act)
{
    const __half* Bt   = (blockIdx.z == 0) ? W0 : (blockIdx.z == 1 ? W1 : W2);
    const float*  bias = (blockIdx.z == 0) ? bi0 : (blockIdx.z == 1 ? bi1 : bi2);
    float*        Cf   = (blockIdx.z == 0) ? Cf0 : (blockIdx.z == 1 ? Cf1 : Cf2);
    __half*       Ch   = (blockIdx.z == 0) ? Ch0 : (blockIdx.z == 1 ? Ch1 : Ch2);

    constexpr int ASZ = BM  * HST;
    constexpr int BSZ = 128 * HST;
    constexpr int SSZ = ASZ + BSZ;       // halves per stage
    extern __shared__ __half smh[];

    const int tid  = threadIdx.x;
    const int row0 = blockIdx.y * BM;
    const int col0 = blockIdx.x * 128;

    const int warp = tid >> 5, lane = tid & 31;
    const int wm = warp >> 2, wn = warp & 3;
    const int grp = lane >> 2, tg = lane & 3;

    const int lrowA = lane & 15;
    const int lcolA = (lane >> 4) * 8;
    const int lrowB = (lane & 7) + ((lane >> 4) & 1) * 8;
    const int lcolB = ((lane >> 3) & 1) * 8;

    const unsigned smemBase = (unsigned)__cvta_generic_to_shared(smh);
    unsigned offA[MT], offB[2];
    #pragma unroll
    for (int mt = 0; mt < MT; mt++)
        offA[mt] = (unsigned)(((wm*(BM/2) + mt*16 + lrowA)*HST + lcolA) * 2);
    #pragma unroll
    for (int p = 0; p < 2; p++)
        offB[p] = (unsigned)(((wn*32 + p*16 + lrowB)*HST + lcolB) * 2 + ASZ*2);

    float acc[MT][4][4];
    #pragma unroll
    for (int mt = 0; mt < MT; mt++)
        #pragma unroll
        for (int nt = 0; nt < 4; nt++)
            #pragma unroll
            for (int c = 0; c < 4; c++) acc[mt][nt][c] = 0.f;

    const __half* Ag = A  + (size_t)row0 * K;
    const __half* Bg = Bt + (size_t)col0 * K;

    auto issue = [&](int it, int stg) {
        __half* As = smh + stg * SSZ;
        __half* Bs = As + ASZ;
        const int kk = it * 64;
        #pragma unroll
        for (int p = 0; p < BM*8/256; p++) {
            int idx = tid + p*256;
            int r = idx >> 3, c8 = (idx & 7) << 3;
            cp16(&As[r*HST + c8], Ag + (size_t)r*K + kk + c8);
        }
        #pragma unroll
        for (int p = 0; p < 4; p++) {
            int idx = tid + p*256;
            int n = idx >> 3, c8 = (idx & 7) << 3;
            cp16(&Bs[n*HST + c8], Bg + (size_t)n*K + kk + c8);
        }
        cp_commit();
    };

    const int nIter = K >> 6;
    issue(0, 0);
    issue(1, 1);

    int stg = 0;
    for (int it = 0; it < nIter; it++) {
        if (it + 1 < nIter) cp_wait<1>(); else cp_wait<0>();
        __syncthreads();                       // all reads of stage (it-1)%3 done
        if (it + 2 < nIter) {
            int ns = stg + 2; if (ns >= 3) ns -= 3;
            issue(it + 2, ns);                 // overwrites stage (it-1)%3
        }

        const unsigned bufBase = smemBase + (unsigned)(stg * SSZ * 2);

        #pragma unroll
        for (int ks = 0; ks < 4; ks++) {
            const unsigned kb = (unsigned)(ks * 32);
            unsigned af[MT][4], bf0[4], bf1[4];
            #pragma unroll
            for (int mt = 0; mt < MT; mt++)
                LDSM4(af[mt], bufBase + offA[mt] + kb);
            LDSM4(bf0, bufBase + offB[0] + kb);
            LDSM4(bf1, bufBase + offB[1] + kb);
            #pragma unroll
            for (int mt = 0; mt < MT; mt++) {
                MMA_F16(acc[mt][0], af[mt], (bf0 + 0));
                MMA_F16(acc[mt][1], af[mt], (bf0 + 2));
                MMA_F16(acc[mt][2], af[mt], (bf1 + 0));
                MMA_F16(acc[mt][3], af[mt], (bf1 + 2));
            }
        }
        if (++stg == 3) stg = 0;
    }

    #pragma unroll
    for (int mt = 0; mt < MT; mt++) {
        #pragma unroll
        for (int nt = 0; nt < 4; nt++) {
            int r0 = row0 + wm*(BM/2) + mt*16 + grp;
            int r1 = r0 + 8;
            int c  = col0 + wn*32 + nt*8 + 2*tg;
            float b0 = bias[c], b1 = bias[c+1];
            float v00 = acc[mt][nt][0] + b0, v01 = acc[mt][nt][1] + b1;
            float v10 = acc[mt][nt][2] + b0, v11 = acc[mt][nt][3] + b1;
            if (res) {
                v00 += res[(size_t)r0*N + c];     v01 += res[(size_t)r0*N + c + 1];
                v10 += res[(size_t)r1*N + c];     v11 += res[(size_t)r1*N + c + 1];
            }
            if (act) {
                v00 = 0.5f*v00*(1.0f + erff(v00*0.70710678118654752f));
                v01 = 0.5f*v01*(1.0f + erff(v01*0.70710678118654752f));
                v10 = 0.5f*v10*(1.0f + erff(v10*0.70710678118654752f));
                v11 = 0.5f*v11*(1.0f + erff(v11*0.70710678118654752f));
            }
            if (Cf) {
                *(float2*)&Cf[(size_t)r0*N + c] = make_float2(v00, v01);
                *(float2*)&Cf[(size_t)r1*N + c] = make_float2(v10, v11);
            }
            if (Ch) {
                *(__half2*)&Ch[(size_t)r0*N + c] = __floats2half2_rn(v00, v01);
                *(__half2*)&Ch[(size_t)r1*N + c] = __floats2half2_rn(v10, v11);
            }
        }
    }
}

// ---------------- fp16 fused attention (phase-1 LDSM, phase-2 scalar) --------
#define AT_KOFF 0
#define AT_QOFF (256*72)
#define AT_VOFF (256*72 + 64*72)
#define AT_FOFF (AT_VOFF + 64*264)
#define AT_SMEM (AT_FOFF*2 + (256 + 256 + 256)*4)

__global__ __launch_bounds__(256, 2) void attn_h()
{
    const int qt = blockIdx.x, h = blockIdx.y, b = blockIdx.z;
    const int q0 = qt * 64;
    const int tid = threadIdx.x;
    const int warp = tid >> 5, lane = tid & 31;
    const int grp = lane >> 2, tg = lane & 3;
    const int wm = warp >> 2, wn = warp & 3;

    extern __shared__ __half smh[];
    __half* Ks = smh + AT_KOFF;
    __half* Qs = smh + AT_QOFF;
    __half* Vt = smh + AT_VOFF;
    __half* Ps = smh;
    float* fb     = (float*)(smh + AT_FOFF);
    float* bias_s = fb;
    float* pmax   = fb + 256;
    float* psum   = fb + 512;

    const __half* Kg = g_kh + (size_t)(b*S_)*H_ + h*D_;
    #pragma unroll
    for (int i = 0; i < 8; i++) {
        int idx = i*256 + tid;
        int r = idx >> 3, c = (idx & 7) << 3;
        cp16(&Ks[r*72 + c], Kg + (size_t)r*H_ + c);
    }
    const __half* Qg = g_qh + (size_t)(b*S_ + q0)*H_ + h*D_;
    #pragma unroll
    for (int i = 0; i < 2; i++) {
        int idx = i*256 + tid;
        int r = idx >> 3, c = (idx & 7) << 3;
        cp16(&Qs[r*72 + c], Qg + (size_t)r*H_ + c);
    }
    cp_commit();

    const __half* Vg = g_vh + (size_t)(b*S_)*H_ + h*D_;
    #pragma unroll
    for (int i = 0; i < 8; i++) {
        int idx = i*256 + tid;
        int k = idx >> 3, d = (idx & 7) << 3;
        uint4 v = *(const uint4*)(Vg + (size_t)k*H_ + d);
        __half hv[8];
        *(uint4*)hv = v;
        #pragma unroll
        for (int j = 0; j < 8; j++) Vt[(d+j)*264 + k] = hv[j];
    }
    bias_s[tid] = g_bias[b*S_ + tid];
    cp_wait<0>();
    __syncthreads();

    // ---- phase 1: scores = Q @ K^T (ldmatrix fragments, verified stride-72) --
    float acc1[2][8][4];
    #pragma unroll
    for (int mt = 0; mt < 2; mt++)
        #pragma unroll
        for (int nt = 0; nt < 8; nt++)
            #pragma unroll
            for (int c = 0; c < 4; c++) acc1[mt][nt][c] = 0.f;

    {
        const int lrowA = lane & 15;
        const int lcolA = (lane >> 4) * 8;
        const int lrowB = (lane & 7) + ((lane >> 4) & 1) * 8;
        const int lcolB = ((lane >> 3) & 1) * 8;
        const unsigned smemBase = (unsigned)__cvta_generic_to_shared(smh);

        unsigned offQ[2], offK[4];
        #pragma unroll
        for (int mt = 0; mt < 2; mt++)
            offQ[mt] = (unsigned)(AT_QOFF*2 + ((wm*32 + mt*16 + lrowA)*72 + lcolA)*2);
        #pragma unroll
        for (int p = 0; p < 4; p++)
            offK[p] = (unsigned)(((wn*64 + p*16 + lrowB)*72 + lcolB)*2);

        #pragma unroll
        for (int ks = 0; ks < 4; ks++) {
            const unsigned kb = (unsigned)(ks * 32);
            unsigned af[2][4], bf[4][4];
            #pragma unroll
            for (int mt = 0; mt < 2; mt++)
                LDSM4(af[mt], smemBase + offQ[mt] + kb);
            #pragma unroll
            for (int p = 0; p < 4; p++)
                LDSM4(bf[p], smemBase + offK[p] + kb);
            #pragma unroll
            for (int mt = 0; mt < 2; mt++)
                #pragma unroll
                for (int p = 0; p < 4; p++) {
                    MMA_F16(acc1[mt][p*2],   af[mt], (bf[p] + 0));
                    MMA_F16(acc1[mt][p*2+1], af[mt], (bf[p] + 2));
                }
        }
    }

    // ---- scale + bias in regs; row max via shfl + smem ----
    float rmax[2][2];
    #pragma unroll
    for (int mt = 0; mt < 2; mt++) { rmax[mt][0] = -1e30f; rmax[mt][1] = -1e30f; }
    #pragma unroll
    for (int mt = 0; mt < 2; mt++)
        #pragma unroll
        for (int p = 0; p < 4; p++)
            #pragma unroll
            for (int q = 0; q < 2; q++) {
                int nt = p*2 + q;
                int c = wn*64 + p*16 + q*8 + 2*tg;
                float b0 = bias_s[c], b1 = bias_s[c+1];
                acc1[mt][nt][0] = acc1[mt][nt][0]*0.125f + b0;
                acc1[mt][nt][1] = acc1[mt][nt][1]*0.125f + b1;
                acc1[mt][nt][2] = acc1[mt][nt][2]*0.125f + b0;
                acc1[mt][nt][3] = acc1[mt][nt][3]*0.125f + b1;
                rmax[mt][0] = fmaxf(rmax[mt][0], fmaxf(acc1[mt][nt][0], acc1[mt][nt][1]));
                rmax[mt][1] = fmaxf(rmax[mt][1], fmaxf(acc1[mt][nt][2], acc1[mt][nt][3]));
            }
    #pragma unroll
    for (int mt = 0; mt < 2; mt++)
        #pragma unroll
        for (int hh = 0; hh < 2; hh++) {
            float m = rmax[mt][hh];
            m = fmaxf(m, __shfl_xor_sync(0xffffffffu, m, 1));
            m = fmaxf(m, __shfl_xor_sync(0xffffffffu, m, 2));
            rmax[mt][hh] = m;
        }
    if (tg == 0) {
        #pragma unroll
        for (int mt = 0; mt < 2; mt++) {
            pmax[(wm*32 + mt*16 + grp)*4 + wn]     = rmax[mt][0];
            pmax[(wm*32 + mt*16 + grp + 8)*4 + wn] = rmax[mt][1];
        }
    }
    __syncthreads();   // gates: all K reads done -> Ps alias writable

    // ---- exp (regs), write fp16 P, partial sums ----
    float rsum[2][2] = {{0.f,0.f},{0.f,0.f}};
    #pragma unroll
    for (int mt = 0; mt < 2; mt++) {
        int lr0 = wm*32 + mt*16 + grp, lr1 = lr0 + 8;
        float m0 = fmaxf(fmaxf(pmax[lr0*4+0], pmax[lr0*4+1]), fmaxf(pmax[lr0*4+2], pmax[lr0*4+3]));
        float m1 = fmaxf(fmaxf(pmax[lr1*4+0], pmax[lr1*4+1]), fmaxf(pmax[lr1*4+2], pmax[lr1*4+3]));
        #pragma unroll
        for (int p = 0; p < 4; p++)
            #pragma unroll
            for (int q = 0; q < 2; q++) {
                int nt = p*2 + q;
                int c = wn*64 + p*16 + q*8 + 2*tg;
                float e0 = __expf(acc1[mt][nt][0] - m0);
                float e1 = __expf(acc1[mt][nt][1] - m0);
                float e2 = __expf(acc1[mt][nt][2] - m1);
                float e3 = __expf(acc1[mt][nt][3] - m1);
                rsum[mt][0] += e0 + e1;
                rsum[mt][1] += e2 + e3;
                *(__half2*)&Ps[lr0*264 + c] = __floats2half2_rn(e0, e1);
                *(__half2*)&Ps[lr1*264 + c] = __floats2half2_rn(e2, e3);
            }
    }
    #pragma unroll
    for (int mt = 0; mt < 2; mt++)
        #pragma unroll
        for (int hh = 0; hh < 2; hh++) {
            float s = rsum[mt][hh];
            s += __shfl_xor_sync(0xffffffffu, s, 1);
            s += __shfl_xor_sync(0xffffffffu, s, 2);
            rsum[mt][hh] = s;
        }
    if (tg == 0) {
        #pragma unroll
        for (int mt = 0; mt < 2; mt++) {
            psum[(wm*32 + mt*16 + grp)*4 + wn]     = rsum[mt][0];
            psum[(wm*32 + mt*16 + grp + 8)*4 + wn] = rsum[mt][1];
        }
    }
    __syncthreads();

    // ---- phase 2: ctx = P @ V (scalar fragment loads; stride-264 quarantined)
    float acc2[2][2][4];
    #pragma unroll
    for (int mt = 0; mt < 2; mt++)
        #pragma unroll
        for (int nt = 0; nt < 2; nt++)
            #pragma unroll
            for (int c = 0; c < 4; c++) acc2[mt][nt][c] = 0.f;

    {
        const unsigned* Pw = (const unsigned*)Ps;
        const unsigned* Vw = (const unsigned*)Vt;
        #pragma unroll 4
        for (int ks = 0; ks < 16; ks++) {
            const int kw = ks * 8;
            unsigned af[2][4], bf[2][2];
            #pragma unroll
            for (int mt = 0; mt < 2; mt++) {
                const unsigned* Ar = Pw + (wm*32 + mt*16 + grp)*132;
                af[mt][0] = Ar[kw + tg];
                af[mt][1] = Ar[8*132 + kw + tg];
                af[mt][2] = Ar[kw + tg + 4];
                af[mt][3] = Ar[8*132 + kw + tg + 4];
            }
            #pragma unroll
            for (int nt = 0; nt < 2; nt++) {
                const unsigned* Br = Vw + (wn*16 + nt*8 + grp)*132;
                bf[nt][0] = Br[kw + tg];
                bf[nt][1] = Br[kw + tg + 4];
            }
            #pragma unroll
            for (int mt = 0; mt < 2; mt++)
                #pragma unroll
                for (int nt = 0; nt < 2; nt++)
                    MMA_F16(acc2[mt][nt], af[mt], bf[nt]);
        }
    }

    #pragma unroll
    for (int mt = 0; mt < 2; mt++) {
        int lr0 = wm*32 + mt*16 + grp, lr1 = lr0 + 8;
        float i0 = 1.0f / (psum[lr0*4+0] + psum[lr0*4+1] + psum[lr0*4+2] + psum[lr0*4+3]);
        float i1 = 1.0f / (psum[lr1*4+0] + psum[lr1*4+1] + psum[lr1*4+2] + psum[lr1*4+3]);
        #pragma unroll
        for (int nt = 0; nt < 2; nt++) {
            int c = wn*16 + nt*8 + 2*tg;
            __half* o0 = g_ctxh + (size_t)(b*S_ + q0 + lr0)*H_ + h*D_ + c;
            __half* o1 = g_ctxh + (size_t)(b*S_ + q0 + lr1)*H_ + h*D_ + c;
            *(__half2*)o0 = __floats2half2_rn(acc2[mt][nt][0]*i0, acc2[mt][nt][1]*i0);
            *(__half2*)o1 = __floats2half2_rn(acc2[mt][nt][2]*i1, acc2[mt][nt][3]*i1);
        }
    }
}

// ---------------- stable compaction order per batch --------------------------
__global__ __launch_bounds__(256) void order_kernel(const int* __restrict__ valid)
{
    int b = blockIdx.x, t = threadIdx.x;
    __shared__ int sc[256];
    __shared__ int ord[256];
    int v = valid[b*S_ + t];
    sc[t] = v; __syncthreads();
    for (int off = 1; off < 256; off <<= 1) {
        int x = (t >= off) ? sc[t - off] : 0;
        __syncthreads();
        sc[t] += x;
        __syncthreads();
    }
    ord[t] = -1; __syncthreads();
    if (v) ord[sc[t] - v] = t;
    __syncthreads();
    g_order[b*S_ + t] = ord[t];
}

__global__ __launch_bounds__(256) void compact_kernel()
{
    int row = blockIdx.x;
    int b = row / S_;
    int src = g_order[row];
    int t = threadIdx.x;
    if (src < 0) {
        for (int e = t; e < H_; e += 256) g_cmp[row*H_ + e] = 0.f;
    } else {
        const float* xp = g_h + (b*S_ + src)*H_;
        for (int e = t; e < H_; e += 256) g_cmp[row*H_ + e] = xp[e];
    }
}

// ---------------- classifier + softmax ---------------------------------------
__global__ __launch_bounds__(256) void clf_kernel(
    const float* __restrict__ W, const float* __restrict__ bias,
    float* __restrict__ outp)
{
    int row = blockIdx.x, t = threadIdx.x;
    __shared__ float red[256][NL_ + 1];
    float p[NL_];
    #pragma unroll
    for (int c = 0; c < NL_; c++) p[c] = 0.f;
    for (int e = t; e < H_; e += 256) {
        float x = g_cmp[row*H_ + e];
        #pragma unroll
        for (int c = 0; c < NL_; c++) p[c] = fmaf(x, W[e*NL_ + c], p[c]);
    }
    #pragma unroll
    for (int c = 0; c < NL_; c++) red[t][c] = p[c];
    __syncthreads();
    for (int st = 128; st > 0; st >>= 1) {
        if (t < st)
            #pragma unroll
            for (int c = 0; c < NL_; c++) red[t][c] += red[t+st][c];
        __syncthreads();
    }
    if (t == 0) {
        float l[NL_], mx = -1e30f, sum = 0.f;
        #pragma unroll
        for (int c = 0; c < NL_; c++) { l[c] = red[0][c] + bias[c]; mx = fmaxf(mx, l[c]); }
        #pragma unroll
        for (int c = 0; c < NL_; c++) { l[c] = expf(l[c] - mx); sum += l[c]; }
        float inv = 1.0f / sum;
        #pragma unroll
        for (int c = 0; c < NL_; c++) outp[row*NL_ + c] = l[c] * inv;
    }
}

// ---------------- launch --------------------------------------------------
extern "C" void kernel_launch(void* const* d_in, const int* in_sizes, int n_in,
                              void* d_out, int out_size)
{
    const int*   ids   = (const int*)  d_in[0];
    const int*   mask  = (const int*)  d_in[1];
    const int*   types = (const int*)  d_in[2];
    const int*   valid = (const int*)  d_in[3];
    const float* we    = (const float*)d_in[4];
    const float* pe    = (const float*)d_in[5];
    const float* te    = (const float*)d_in[6];
    const float* elg   = (const float*)d_in[7];
    const float* elb   = (const float*)d_in[8];
    const float* Wq    = (const float*)d_in[9];
    const float* bq    = (const float*)d_in[10];
    const float* Wk    = (const float*)d_in[11];
    const float* bk    = (const float*)d_in[12];
    const float* Wv    = (const float*)d_in[13];
    const float* bv    = (const float*)d_in[14];
    const float* Wo    = (const float*)d_in[15];
    const float* bo    = (const float*)d_in[16];
    const float* l1g   = (const float*)d_in[17];
    const float* l1b   = (const float*)d_in[18];
    const float* Wi    = (const float*)d_in[19];
    const float* bi    = (const float*)d_in[20];
    const float* Wo2   = (const float*)d_in[21];
    const float* bo2   = (const float*)d_in[22];
    const float* l2g   = (const float*)d_in[23];
    const float* l2b   = (const float*)d_in[24];
    const float* cW    = (const float*)d_in[25];
    const float* cb    = (const float*)d_in[26];
    float* outp = (float*)d_out;

    float *ph, *ptmp;
    __half *phh, *pqh, *pkh, *pvh, *pctxh, *pffh;
    __half *tq, *tk, *tv, *to, *ti, *to2;
    cudaGetSymbolAddress((void**)&ph,    g_h);
    cudaGetSymbolAddress((void**)&phh,   g_hh);
    cudaGetSymbolAddress((void**)&pqh,   g_qh);
    cudaGetSymbolAddress((void**)&pkh,   g_kh);
    cudaGetSymbolAddress((void**)&pvh,   g_vh);
    cudaGetSymbolAddress((void**)&pctxh, g_ctxh);
    cudaGetSymbolAddress((void**)&ptmp,  g_tmp);
    cudaGetSymbolAddress((void**)&pffh,  g_ffh);
    cudaGetSymbolAddress((void**)&tq,    g_tWq);
    cudaGetSymbolAddress((void**)&tk,    g_tWk);
    cudaGetSymbolAddress((void**)&tv,    g_tWv);
    cudaGetSymbolAddress((void**)&to,    g_tWo);
    cudaGetSymbolAddress((void**)&ti,    g_tWi);
    cudaGetSymbolAddress((void**)&to2,   g_tWo2);

    cudaFuncSetAttribute(attn_h,
                         cudaFuncAttributeMaxDynamicSharedMemorySize, AT_SMEM);

    const int smem32  = 3 * (32*HST  + 128*HST) * 2;   // 69,120 B (3 CTAs/SM ok)
    const int smem128 = 3 * (128*HST + 128*HST) * 2;   // 110,592 B (2 CTAs/SM)
    cudaFuncSetAttribute((const void*)gemm_h<32,1,3>,
                         cudaFuncAttributeMaxDynamicSharedMemorySize, smem32);
    cudaFuncSetAttribute((const void*)gemm_h<128,4,2>,
                         cudaFuncAttributeMaxDynamicSharedMemorySize, smem128);

    dim3 gQKV(H_ / 128,  M_ / 128, 3);   // (6, 16, 3) = 288 blocks, BM=128
    dim3 gH  (H_ / 128,  M_ / 32, 1);    // (6, 64) = 384 blocks, BM=32, 3/SM
    dim3 gFF (FF_ / 128, M_ / 128, 1);   // (24, 16) = 384 blocks, BM=128

    embed_kernel<<<M_, 256>>>(ids, types, we, pe, te, elg, elb);
    bias_kernel<<<(M_ + 255)/256, 256>>>(mask);
    cvtT_kernel<<<dim3(H_/32,  H_/32, L_), 256>>>(Wq,  tq,  H_,  H_);
    cvtT_kernel<<<dim3(H_/32,  H_/32, L_), 256>>>(Wk,  tk,  H_,  H_);
    cvtT_kernel<<<dim3(H_/32,  H_/32, L_), 256>>>(Wv,  tv,  H_,  H_);

    for (int l = 0; l < L_; l++) {
        const __half* wq = tq  + (size_t)l*H_*H_;
        const __half* wk = tk  + (size_t)l*H_*H_;
        const __half* wv = tv  + (size_t)l*H_*H_;
        const __half* wo = to  + (size_t)l*H_*H_;
        const __half* wi = ti  + (size_t)l*H_*FF_;
        const __half* w2 = to2 + (size_t)l*FF_*H_;

        gemm_h<128,4,2><<<gQKV, 256, smem128>>>(phh, wq, wk, wv,
                                bq + l*H_, bk + l*H_, bv + l*H_,
                                nullptr, nullptr, nullptr,
                                pqh, pkh, pvh, nullptr, M_, H_, H_, 0);

        if (l == 0) {
            cvtT_kernel<<<dim3(H_/32,  H_/32, L_), 256>>>(Wo,  to,  H_,  H_);
            cvtT_kernel<<<dim3(FF_/32, H_/32, L_), 256>>>(Wi,  ti,  H_,  FF_);
            cvtT_kernel<<<dim3(H_/32,  FF_/32, L_), 256>>>(Wo2, to2, FF_, H_);
        }

        attn_h<<<dim3(S_/64, NH_, B_), 256, AT_SMEM>>>();

        gemm_h<32,1,3><<<gH, 256, smem32>>>(pctxh, wo, wo, wo,
                              bo + l*H_, bo + l*H_, bo + l*H_,
                              ptmp, ptmp, ptmp,
                              nullptr, nullptr, nullptr, ph, M_, H_, H_, 0);
        ln_kernel<<<M_, 256>>>(ptmp, l1g + l*H_, l1b + l*H_, ph, phh);

        gemm_h<128,4,2><<<gFF, 256, smem128>>>(phh, wi, wi, wi,
                               bi + l*FF_, bi + l*FF_, bi + l*FF_,
                               nullptr, nullptr, nullptr,
                               pffh, pffh, pffh, nullptr, M_, FF_, H_, 1);
        gemm_h<32,1,3><<<gH, 256, smem32>>>(pffh, w2, w2, w2,
                              bo2 + l*H_, bo2 + l*H_, bo2 + l*H_,
                              ptmp, ptmp, ptmp,
                              nullptr, nullptr, nullptr, ph, M_, H_, FF_, 0);
        ln_kernel<<<M_, 256>>>(ptmp, l2g + l*H_, l2b + l*H_, ph, phh);
    }

    order_kernel<<<B_, 256>>>(valid);
    compact_kernel<<<M_, 256>>>();
    clf_kernel<<<M_, 256>>>(cW, cb, outp);
}